// round 4
// baseline (speedup 1.0000x reference)
#include <cuda_runtime.h>
#include <cstddef>

static constexpr int T_  = 32;
static constexpr int B_  = 512;
static constexpr int NS_ = 64;
static constexpr int NC_ = 32;
static constexpr int SZ_ = 96;   // NS + NC

// ---------------- scratch (static device globals; no allocation) ----------------
__device__ float g_cback[(size_t)T_ * B_ * SZ_];      // C@xu + c
__device__ float g_costpart[T_ * B_];                 // per (t,b) old-cost contribution
__device__ float g_q0[T_ * B_];
__device__ float g_q1[T_ * B_];
__device__ float g_q2[T_ * B_];
__device__ float g_V[(size_t)B_ * NS_ * NS_];         // value Hessian (carried across t)
__device__ float g_v[B_ * NS_];                       // value gradient
__device__ float g_K[(size_t)T_ * B_ * NC_ * NS_];    // gains
__device__ float g_kv[(size_t)T_ * B_ * NC_];
__device__ float g_z0[(size_t)T_ * B_ * SZ_];         // base rollout [nx;nu] (alpha=0)
__device__ float g_dz[(size_t)T_ * B_ * SZ_];         // d/dalpha of rollout
__device__ float g_alpha[B_];

// ---------------- init: zero V, v ----------------
__global__ void init_kernel() {
    size_t n = (size_t)B_ * NS_ * NS_;
    for (size_t i = blockIdx.x * blockDim.x + threadIdx.x; i < n; i += (size_t)gridDim.x * blockDim.x)
        g_V[i] = 0.f;
    for (size_t i = blockIdx.x * blockDim.x + threadIdx.x; i < (size_t)B_ * NS_; i += (size_t)gridDim.x * blockDim.x)
        g_v[i] = 0.f;
}

// ---------------- prep: c_back = C@xu + c ; old-cost partials ----------------
__global__ void prep_kernel(const float* __restrict__ x, const float* __restrict__ u,
                            const float* __restrict__ C, const float* __restrict__ c) {
    int tb = blockIdx.x;                 // t*B + b
    const float* Cb = C + (size_t)tb * SZ_ * SZ_;
    const float* cb = c + (size_t)tb * SZ_;
    __shared__ float sxu[SZ_];
    __shared__ float sC[SZ_ * 97];
    __shared__ float sred[128];
    int tid = threadIdx.x;

    if (tid < NS_)      sxu[tid] = x[(size_t)tb * NS_ + tid];
    else if (tid < SZ_) sxu[tid] = u[(size_t)tb * NC_ + (tid - NS_)];

    const float4* C4 = (const float4*)Cb;
    for (int i4 = tid; i4 < SZ_ * SZ_ / 4; i4 += 128) {
        float4 v = C4[i4];
        int e = i4 * 4; int r = e / SZ_; int cc = e % SZ_;
        float* dst = &sC[r * 97 + cc];
        dst[0] = v.x; dst[1] = v.y; dst[2] = v.z; dst[3] = v.w;
    }
    __syncthreads();

    float part = 0.f;
    if (tid < SZ_) {
        float acc = 0.f;
        const float* row = &sC[tid * 97];
#pragma unroll 8
        for (int j = 0; j < SZ_; j++) acc += row[j] * sxu[j];
        float cv = cb[tid];
        g_cback[(size_t)tb * SZ_ + tid] = acc + cv;
        part = sxu[tid] * (0.5f * acc + cv);     // 0.5 xu'Cxu + c'xu
    }
    sred[tid] = part;
    __syncthreads();
    for (int s = 64; s > 0; s >>= 1) { if (tid < s) sred[tid] += sred[tid + s]; __syncthreads(); }
    if (tid == 0) g_costpart[tb] = sred[0];
}

// ---------------- backward Riccati step for one t (512 CTAs, 256 threads) ----------------
static constexpr int BK_SMEM =
    (64 * 65 + 64 * 97 + 64 * 97 + 32 * 100 + 32 * 65 + 32 * 65 + 96 + 64 + 32) * 4;

__global__ void backward_kernel(int t, const float* __restrict__ C, const float* __restrict__ F) {
    extern __shared__ float sm[];
    float* sV   = sm;                 // 64 x 65   (V in; V_new out)
    float* sF   = sV + 64 * 65;       // 64 x 97
    float* sW   = sF + 64 * 97;       // 64 x 97   W = V F
    float* sAug = sW + 64 * 97;       // 32 x 100  [Quu | Qux | qu]
    float* sQxS = sAug + 32 * 100;    // 32 x 65   saved Qux
    float* sK   = sQxS + 32 * 65;     // 32 x 65
    float* sq   = sK + 32 * 65;       // 96
    float* sv   = sq + 96;            // 64
    float* skv  = sv + 64;            // 32

    int b = blockIdx.x;
    int tid = threadIdx.x, lane = tid & 31, w = tid >> 5;
    size_t tb = (size_t)t * B_ + b;
    const float* Cb = C + tb * SZ_ * SZ_;
    const float* Fb = F + tb * NS_ * SZ_;

    for (int i = tid; i < NS_ * NS_; i += 256) { int r = i >> 6, cc = i & 63; sV[r * 65 + cc] = g_V[(size_t)b * NS_ * NS_ + i]; }
    for (int i = tid; i < NS_ * SZ_; i += 256) { int r = i / 96, cc = i % 96; sF[r * 97 + cc] = Fb[i]; }
    if (tid < NS_) sv[tid] = g_v[b * NS_ + tid];
    __syncthreads();

    // GEMM1: W[m][s] = sum_n V[m][n] F[n][s]
    for (int mi = 0; mi < 4; mi++) {
        int m0 = w * 8 + mi * 2;
        float a00 = 0, a01 = 0, a02 = 0, a10 = 0, a11 = 0, a12 = 0;
        const float* v0 = &sV[m0 * 65];
        const float* v1 = &sV[(m0 + 1) * 65];
#pragma unroll 4
        for (int n = 0; n < 64; n++) {
            float b0 = sF[n * 97 + lane];
            float b1 = sF[n * 97 + lane + 32];
            float b2 = sF[n * 97 + lane + 64];
            float x0 = v0[n], x1 = v1[n];
            a00 += x0 * b0; a01 += x0 * b1; a02 += x0 * b2;
            a10 += x1 * b0; a11 += x1 * b1; a12 += x1 * b2;
        }
        sW[m0 * 97 + lane] = a00; sW[m0 * 97 + lane + 32] = a01; sW[m0 * 97 + lane + 64] = a02;
        sW[(m0 + 1) * 97 + lane] = a10; sW[(m0 + 1) * 97 + lane + 32] = a11; sW[(m0 + 1) * 97 + lane + 64] = a12;
    }
    // q[s] = c_back[s] + sum_n F[n][s] v[n]
    if (tid < SZ_) {
        float acc = 0.f;
#pragma unroll 8
        for (int n = 0; n < 64; n++) acc += sF[n * 97 + tid] * sv[n];
        sq[tid] = acc + g_cback[tb * SZ_ + tid];
    }
    __syncthreads();

    // GEMM2: Qrow[i][s] = C[(64+i),s] + sum_n F[n][64+i] W[n][s], i<32  -> scatter into Aug / QuxSave
    for (int mi = 0; mi < 2; mi++) {
        int i0 = w * 4 + mi * 2;
        float a00 = 0, a01 = 0, a02 = 0, a10 = 0, a11 = 0, a12 = 0;
#pragma unroll 4
        for (int n = 0; n < 64; n++) {
            float x0 = sF[n * 97 + 64 + i0];
            float x1 = sF[n * 97 + 64 + i0 + 1];
            float b0 = sW[n * 97 + lane];
            float b1 = sW[n * 97 + lane + 32];
            float b2 = sW[n * 97 + lane + 64];
            a00 += x0 * b0; a01 += x0 * b1; a02 += x0 * b2;
            a10 += x1 * b0; a11 += x1 * b1; a12 += x1 * b2;
        }
        a00 += Cb[(64 + i0) * 96 + lane];
        a01 += Cb[(64 + i0) * 96 + lane + 32];
        a02 += Cb[(64 + i0) * 96 + lane + 64];
        a10 += Cb[(64 + i0 + 1) * 96 + lane];
        a11 += Cb[(64 + i0 + 1) * 96 + lane + 32];
        a12 += Cb[(64 + i0 + 1) * 96 + lane + 64];
        // scatter: s<64 -> Qux (Aug cols 32..95 + save); s>=64 -> Quu (Aug cols 0..31)
        sQxS[i0 * 65 + lane] = a00;        sAug[i0 * 100 + 32 + lane] = a00;
        sQxS[i0 * 65 + lane + 32] = a01;   sAug[i0 * 100 + 64 + lane] = a01;
        sAug[i0 * 100 + lane] = a02;
        sQxS[(i0 + 1) * 65 + lane] = a10;      sAug[(i0 + 1) * 100 + 32 + lane] = a10;
        sQxS[(i0 + 1) * 65 + lane + 32] = a11; sAug[(i0 + 1) * 100 + 64 + lane] = a11;
        sAug[(i0 + 1) * 100 + lane] = a12;
    }
    if (tid < 32) sAug[tid * 100 + 96] = sq[64 + tid];   // qu
    __syncthreads();

    // Gauss-Jordan: Aug -> [I | Quu^{-1}[Qux qu]]  (Quu is SPD, no pivoting needed)
    for (int kp = 0; kp < 32; kp++) {
        float pinv = 1.0f / sAug[kp * 100 + kp];
        for (int j = kp + 1 + tid; j <= 96; j += 256) sAug[kp * 100 + j] *= pinv;
        __syncthreads();
        int r = tid >> 3, sub = tid & 7;
        if (r != kp) {
            float f = sAug[r * 100 + kp];
            for (int j = kp + 1 + sub; j <= 96; j += 8) sAug[r * 100 + j] -= f * sAug[kp * 100 + j];
        }
        __syncthreads();
    }

    // K = -Quu^{-1} Qux ; k = -Quu^{-1} qu   -> smem + global
    float* Kg = g_K + tb * NC_ * NS_;
    for (int i = tid; i < NC_ * NS_; i += 256) {
        int m = i >> 6, j = i & 63;
        float val = -sAug[m * 100 + 32 + j];
        sK[m * 65 + j] = val;
        Kg[i] = val;
    }
    if (tid < NC_) {
        float kv = -sAug[tid * 100 + 96];
        skv[tid] = kv;
        g_kv[tb * NC_ + tid] = kv;
    }
    __syncthreads();

    // V_new[i][j] = C[i][j] + sum_n F[n][i] W[n][j] + sum_m Qux[m][i] K[m][j]   (into sV)
    for (int mi = 0; mi < 4; mi++) {
        int i0 = w * 8 + mi * 2;
        float a00 = 0, a01 = 0, a10 = 0, a11 = 0;
#pragma unroll 4
        for (int n = 0; n < 64; n++) {
            float x0 = sF[n * 97 + i0], x1 = sF[n * 97 + i0 + 1];
            float b0 = sW[n * 97 + lane], b1 = sW[n * 97 + lane + 32];
            a00 += x0 * b0; a01 += x0 * b1;
            a10 += x1 * b0; a11 += x1 * b1;
        }
#pragma unroll 4
        for (int m = 0; m < 32; m++) {
            float x0 = sQxS[m * 65 + i0], x1 = sQxS[m * 65 + i0 + 1];
            float b0 = sK[m * 65 + lane], b1 = sK[m * 65 + lane + 32];
            a00 += x0 * b0; a01 += x0 * b1;
            a10 += x1 * b0; a11 += x1 * b1;
        }
        a00 += Cb[i0 * 96 + lane];        a01 += Cb[i0 * 96 + lane + 32];
        a10 += Cb[(i0 + 1) * 96 + lane];  a11 += Cb[(i0 + 1) * 96 + lane + 32];
        sV[i0 * 65 + lane] = a00;         sV[i0 * 65 + lane + 32] = a01;
        sV[(i0 + 1) * 65 + lane] = a10;   sV[(i0 + 1) * 65 + lane + 32] = a11;
    }
    // v_new[i] = qx[i] + sum_m Qux[m][i] k[m]
    float vnew = 0.f;
    if (tid < NS_) {
        float acc = sq[tid];
#pragma unroll 4
        for (int m = 0; m < 32; m++) acc += sQxS[m * 65 + tid] * skv[m];
        vnew = acc;
    }
    __syncthreads();
    for (int i = tid; i < NS_ * NS_; i += 256) { int r = i >> 6, cc = i & 63; g_V[(size_t)b * NS_ * NS_ + i] = sV[r * 65 + cc]; }
    if (tid < NS_) g_v[b * NS_ + tid] = vnew;
}

// ---------------- rollout: base (alpha=0) and direction trajectories ----------------
__global__ void rollout_kernel(const float* __restrict__ x, const float* __restrict__ u,
                               const float* __restrict__ x_init, const float* __restrict__ F) {
    int b = blockIdx.x;
    int tid = threadIdx.x;   // 128
    __shared__ float sF[64 * 97];
    __shared__ float sK[32 * 65];
    __shared__ float sk[32], su[32], sxn[64];
    __shared__ float nx0[64], dx0[64], dnx[64];
    __shared__ float sz0[96], szd[96];
    __shared__ float nxn[64], dnxn[64];

    if (tid < 64) { nx0[tid] = x_init[b * 64 + tid]; dx0[tid] = 0.f; dnx[tid] = 0.f; }
    __syncthreads();

    for (int t = 0; t < T_; t++) {
        size_t tb = (size_t)t * B_ + b;
        const float* Fb = F + tb * NS_ * SZ_;
        for (int i = tid; i < NS_ * SZ_; i += 128) sF[(i / 96) * 97 + i % 96] = Fb[i];
        const float* Kg = g_K + tb * NC_ * NS_;
        for (int i = tid; i < NC_ * NS_; i += 128) sK[(i >> 6) * 65 + (i & 63)] = Kg[i];
        if (tid < NC_) { sk[tid] = g_kv[tb * NC_ + tid]; su[tid] = u[tb * NC_ + tid]; }
        int tn = (t < T_ - 1) ? t + 1 : T_ - 1;
        if (tid < NS_) sxn[tid] = x[((size_t)tn * B_ + b) * NS_ + tid];
        __syncthreads();

        // controls
        if (tid < NC_) {
            float a0 = su[tid], a1 = sk[tid];
#pragma unroll 8
            for (int n = 0; n < 64; n++) { float kk = sK[tid * 65 + n]; a0 += kk * dx0[n]; a1 += kk * dnx[n]; }
            sz0[64 + tid] = a0; szd[64 + tid] = a1;
        }
        if (tid < NS_) { sz0[tid] = nx0[tid]; szd[tid] = dnx[tid]; }
        __syncthreads();

        // record entry state+control
        if (tid < SZ_) { g_z0[tb * SZ_ + tid] = sz0[tid]; g_dz[tb * SZ_ + tid] = szd[tid]; }

        // next state
        if (tid < NS_) {
            float a0 = 0.f, a1 = 0.f;
            const float* fr = &sF[tid * 97];
#pragma unroll 8
            for (int s = 0; s < 96; s++) { float fv = fr[s]; a0 += fv * sz0[s]; a1 += fv * szd[s]; }
            nxn[tid] = a0; dnxn[tid] = a1;
        }
        __syncthreads();
        if (tid < NS_) { nx0[tid] = nxn[tid]; dx0[tid] = nxn[tid] - sxn[tid]; dnx[tid] = dnxn[tid]; }
        __syncthreads();
    }
}

// ---------------- cost quadratic coefficients: cost(a) = q0 + a q1 + a^2 q2 ----------------
__global__ void coef_kernel(const float* __restrict__ C, const float* __restrict__ c) {
    int tb = blockIdx.x;
    const float* Cb = C + (size_t)tb * SZ_ * SZ_;
    const float* cb = c + (size_t)tb * SZ_;
    __shared__ float sC[SZ_ * 97];
    __shared__ float sz[96], sd[96];
    __shared__ float r0[128], r1[128], r2[128];
    int tid = threadIdx.x;

    if (tid < SZ_) { sz[tid] = g_z0[(size_t)tb * SZ_ + tid]; sd[tid] = g_dz[(size_t)tb * SZ_ + tid]; }
    const float4* C4 = (const float4*)Cb;
    for (int i4 = tid; i4 < SZ_ * SZ_ / 4; i4 += 128) {
        float4 v = C4[i4];
        int e = i4 * 4; int r = e / SZ_; int cc = e % SZ_;
        float* dst = &sC[r * 97 + cc];
        dst[0] = v.x; dst[1] = v.y; dst[2] = v.z; dst[3] = v.w;
    }
    __syncthreads();

    float p0 = 0.f, p1 = 0.f, p2 = 0.f;
    if (tid < SZ_) {
        float y0 = 0.f, yd = 0.f;
        const float* row = &sC[tid * 97];
#pragma unroll 8
        for (int j = 0; j < SZ_; j++) { float cv = row[j]; y0 += cv * sz[j]; yd += cv * sd[j]; }
        float cv = cb[tid];
        p0 = sz[tid] * (0.5f * y0 + cv);
        p1 = sd[tid] * (y0 + cv);
        p2 = 0.5f * sd[tid] * yd;
    }
    r0[tid] = p0; r1[tid] = p1; r2[tid] = p2;
    __syncthreads();
    for (int s = 64; s > 0; s >>= 1) {
        if (tid < s) { r0[tid] += r0[tid + s]; r1[tid] += r1[tid + s]; r2[tid] += r2[tid + s]; }
        __syncthreads();
    }
    if (tid == 0) { g_q0[tb] = r0[0]; g_q1[tb] = r1[0]; g_q2[tb] = r2[0]; }
}

// ---------------- line search resolve + cost output ----------------
__global__ void ls_kernel(float* __restrict__ out_cost) {
    int b = threadIdx.x;  // 512
    float old = 0.f, A0 = 0.f, A1 = 0.f, A2 = 0.f;
    for (int t = 0; t < T_; t++) {
        int idx = t * B_ + b;
        old += g_costpart[idx];
        A0 += g_q0[idx]; A1 += g_q1[idx]; A2 += g_q2[idx];
    }
    float alpha = 1.f;
    // iterations 0..2 update alpha used at iteration 3 (MAX_LS = 4)
#pragma unroll
    for (int i = 0; i < 3; i++) {
        float cst = A0 + alpha * (A1 + alpha * A2);
        if (cst > old) alpha *= 0.5f;
    }
    float cur = A0 + alpha * (A1 + alpha * A2);
    g_alpha[b] = alpha;
    out_cost[b] = cur;
}

// ---------------- final outputs: new_x, new_u ----------------
__global__ void out_kernel(float* __restrict__ out) {
    size_t total = (size_t)T_ * B_ * SZ_;
    for (size_t idx = blockIdx.x * (size_t)blockDim.x + threadIdx.x; idx < total;
         idx += (size_t)gridDim.x * blockDim.x) {
        size_t tb = idx / SZ_;
        int s = (int)(idx % SZ_);
        int b = (int)(tb % B_);
        float val = g_z0[idx] + g_alpha[b] * g_dz[idx];
        if (s < NS_) out[tb * NS_ + s] = val;
        else         out[(size_t)T_ * B_ * NS_ + tb * NC_ + (s - NS_)] = val;
    }
}

// ---------------- launch ----------------
extern "C" void kernel_launch(void* const* d_in, const int* in_sizes, int n_in,
                              void* d_out, int out_size) {
    const float *x = nullptr, *u = nullptr, *xi = nullptr, *C = nullptr, *c = nullptr, *F = nullptr;
    for (int i = 0; i < n_in; i++) {
        long long s = in_sizes[i];
        const float* p = (const float*)d_in[i];
        if      (s == (long long)T_ * B_ * SZ_ * SZ_) C = p;
        else if (s == (long long)T_ * B_ * NS_ * SZ_) F = p;
        else if (s == (long long)T_ * B_ * SZ_)       c = p;
        else if (s == (long long)T_ * B_ * NS_)       x = p;
        else if (s == (long long)T_ * B_ * NC_)       u = p;
        else if (s == (long long)B_ * NS_)            xi = p;
    }
    float* out = (float*)d_out;

    cudaFuncSetAttribute(backward_kernel, cudaFuncAttributeMaxDynamicSharedMemorySize, BK_SMEM);

    init_kernel<<<1024, 256>>>();
    prep_kernel<<<T_ * B_, 128>>>(x, u, C, c);
    for (int t = T_ - 1; t >= 0; t--)
        backward_kernel<<<B_, 256, BK_SMEM>>>(t, C, F);
    rollout_kernel<<<B_, 128>>>(x, u, xi, F);
    coef_kernel<<<T_ * B_, 128>>>(C, c);
    ls_kernel<<<1, B_>>>(out + (size_t)T_ * B_ * (NS_ + NC_));
    out_kernel<<<4096, 256>>>(out);
}

// round 6
// speedup vs baseline: 1.4932x; 1.4932x over previous
#include <cuda_runtime.h>
#include <cstddef>

static constexpr int T_  = 32;
static constexpr int B_  = 512;
static constexpr int NS_ = 64;
static constexpr int NC_ = 32;
static constexpr int SZ_ = 96;   // NS + NC

using ull = unsigned long long;

// ---------------- scratch (static device globals; no allocation) ----------------
__device__ float g_cback[(size_t)T_ * B_ * SZ_];      // C@xu + c
__device__ float g_costpart[T_ * B_];                 // per (t,b) old-cost contribution
__device__ float g_q0[T_ * B_];
__device__ float g_q1[T_ * B_];
__device__ float g_q2[T_ * B_];
__device__ float g_K[(size_t)T_ * B_ * NC_ * NS_];    // gains
__device__ float g_kv[(size_t)T_ * B_ * NC_];
__device__ float g_z0[(size_t)T_ * B_ * SZ_];         // base rollout [nx;nu] (alpha=0)
__device__ float g_dz[(size_t)T_ * B_ * SZ_];         // d/dalpha of rollout
__device__ float g_alpha[B_];

// ---------------- packed f32x2 helpers ----------------
__device__ __forceinline__ void fma2(ull& acc, ull x, ull b) {
    asm("fma.rn.f32x2 %0, %1, %2, %0;" : "+l"(acc) : "l"(x), "l"(b));
}
__device__ __forceinline__ ull pack2(float lo, float hi) {
    ull r;
    asm("mov.b64 %0, {%1, %2};" : "=l"(r) : "f"(lo), "f"(hi));
    return r;
}
__device__ __forceinline__ float2 unpack2(ull v) {
    float2 r;
    asm("mov.b64 {%0, %1}, %2;" : "=f"(r.x), "=f"(r.y) : "l"(v));
    return r;
}

// ---------------- prep: c_back = C@xu + c ; old-cost partials ----------------
__global__ void prep_kernel(const float* __restrict__ x, const float* __restrict__ u,
                            const float* __restrict__ C, const float* __restrict__ c) {
    int tb = blockIdx.x;                 // t*B + b
    const float* Cb = C + (size_t)tb * SZ_ * SZ_;
    const float* cb = c + (size_t)tb * SZ_;
    __shared__ float sxu[SZ_];
    __shared__ float sC[SZ_ * 97];
    __shared__ float sred[128];
    int tid = threadIdx.x;

    if (tid < NS_)      sxu[tid] = x[(size_t)tb * NS_ + tid];
    else if (tid < SZ_) sxu[tid] = u[(size_t)tb * NC_ + (tid - NS_)];

    const float4* C4 = (const float4*)Cb;
    for (int i4 = tid; i4 < SZ_ * SZ_ / 4; i4 += 128) {
        float4 v = C4[i4];
        int e = i4 * 4; int r = e / SZ_; int cc = e % SZ_;
        float* dst = &sC[r * 97 + cc];
        dst[0] = v.x; dst[1] = v.y; dst[2] = v.z; dst[3] = v.w;
    }
    __syncthreads();

    float part = 0.f;
    if (tid < SZ_) {
        float acc = 0.f;
        const float* row = &sC[tid * 97];
#pragma unroll 8
        for (int j = 0; j < SZ_; j++) acc += row[j] * sxu[j];
        float cv = cb[tid];
        g_cback[(size_t)tb * SZ_ + tid] = acc + cv;
        part = sxu[tid] * (0.5f * acc + cv);     // 0.5 xu'Cxu + c'xu
    }
    sred[tid] = part;
    __syncthreads();
    for (int s = 64; s > 0; s >>= 1) { if (tid < s) sred[tid] += sred[tid + s]; __syncthreads(); }
    if (tid == 0) g_costpart[tb] = sred[0];
}

// ---------------- persistent backward Riccati (one CTA per batch, loop over t) ----------------
// smem layout (floats):
static constexpr int OFF_V   = 0;                    // 64 x 68   (V, symmetric)
static constexpr int OFF_F   = OFF_V   + 64 * 68;    // 64 x 100
static constexpr int OFF_W   = OFF_F   + 64 * 100;   // 64 x 100  W = V F
static constexpr int OFF_AUG = OFF_W   + 64 * 100;   // 32 x 100  [Quu | Qux | qu]
static constexpr int OFF_QX  = OFF_AUG + 32 * 100;   // 32 x 68   saved Qux
static constexpr int OFF_K   = OFF_QX  + 32 * 68;    // 32 x 68
static constexpr int OFF_q   = OFF_K   + 32 * 68;    // 96
static constexpr int OFF_v   = OFF_q   + 96;         // 64
static constexpr int OFF_kv  = OFF_v   + 64;         // 32
static constexpr int OFF_di  = OFF_kv  + 32;         // 32
static constexpr int BK_FLOATS = OFF_di + 32;
static constexpr int BK_SMEM = BK_FLOATS * 4;        // ~99.6 KB -> 2 CTAs/SM

__global__ void backward_kernel(const float* __restrict__ C, const float* __restrict__ F) {
    extern __shared__ float sm[];
    float* sV   = sm + OFF_V;
    float* sF   = sm + OFF_F;
    float* sW   = sm + OFF_W;
    float* sAug = sm + OFF_AUG;
    float* sQxS = sm + OFF_QX;
    float* sK   = sm + OFF_K;
    float* sq   = sm + OFF_q;
    float* sv   = sm + OFF_v;
    float* skv  = sm + OFF_kv;
    float* sdin = sm + OFF_di;

    int b = blockIdx.x;
    int tid = threadIdx.x, lane = tid & 31, w = tid >> 5;

    // init V = 0, v = 0
    for (int i = tid; i < 64 * 68; i += 256) sV[i] = 0.f;
    if (tid < NS_) sv[tid] = 0.f;

    for (int t = T_ - 1; t >= 0; t--) {
        size_t tb = (size_t)t * B_ + b;
        const float* Cb = C + tb * SZ_ * SZ_;
        const float* Fb = F + tb * NS_ * SZ_;

        // load F tile (vectorized; rows padded to 100)
        {
            const float4* F4 = (const float4*)Fb;
            for (int i4 = tid; i4 < NS_ * SZ_ / 4; i4 += 256) {
                float4 val = F4[i4];
                int e = i4 * 4; int r = e / 96; int cc = e % 96;
                float* dst = &sF[r * 100 + cc];
                dst[0] = val.x; dst[1] = val.y; dst[2] = val.z; dst[3] = val.w;
            }
        }
        __syncthreads();

        // ---- GEMM1: W[m][s] = sum_n V[m][n] F[n][s]  (x-pairs read via V symmetry)
        {
            int m0 = w * 8;
            ull acc[4][3];
#pragma unroll
            for (int p = 0; p < 4; p++) { acc[p][0] = 0; acc[p][1] = 0; acc[p][2] = 0; }
#pragma unroll 4
            for (int n = 0; n < 64; n++) {
                float b0 = sF[n * 100 + lane];
                float b1 = sF[n * 100 + lane + 32];
                float b2 = sF[n * 100 + lane + 64];
                ull bb0 = pack2(b0, b0), bb1 = pack2(b1, b1), bb2 = pack2(b2, b2);
                const ull* xv = (const ull*)&sV[n * 68 + m0];
#pragma unroll
                for (int p = 0; p < 4; p++) {
                    ull xx = xv[p];
                    fma2(acc[p][0], xx, bb0);
                    fma2(acc[p][1], xx, bb1);
                    fma2(acc[p][2], xx, bb2);
                }
            }
#pragma unroll
            for (int p = 0; p < 4; p++) {
                int m = m0 + 2 * p;
                float2 c0 = unpack2(acc[p][0]);
                float2 c1 = unpack2(acc[p][1]);
                float2 c2 = unpack2(acc[p][2]);
                sW[m * 100 + lane]            = c0.x;
                sW[(m + 1) * 100 + lane]      = c0.y;
                sW[m * 100 + lane + 32]       = c1.x;
                sW[(m + 1) * 100 + lane + 32] = c1.y;
                sW[m * 100 + lane + 64]       = c2.x;
                sW[(m + 1) * 100 + lane + 64] = c2.y;
            }
        }
        // q[s] = c_back[s] + sum_n F[n][s] v[n]
        if (tid < SZ_) {
            float acc = 0.f;
#pragma unroll 8
            for (int n = 0; n < 64; n++) acc += sF[n * 100 + tid] * sv[n];
            sq[tid] = acc + g_cback[tb * SZ_ + tid];
        }
        __syncthreads();

        // ---- GEMM2: Q-rows 64..95: C[(64+i),s] + sum_n F[n][64+i] W[n][s] -> Aug / QxSave
        {
            int i0 = w * 4;
            ull acc[2][3];
#pragma unroll
            for (int p = 0; p < 2; p++) { acc[p][0] = 0; acc[p][1] = 0; acc[p][2] = 0; }
#pragma unroll 4
            for (int n = 0; n < 64; n++) {
                float b0 = sW[n * 100 + lane];
                float b1 = sW[n * 100 + lane + 32];
                float b2 = sW[n * 100 + lane + 64];
                ull bb0 = pack2(b0, b0), bb1 = pack2(b1, b1), bb2 = pack2(b2, b2);
                const ull* xv = (const ull*)&sF[n * 100 + 64 + i0];
#pragma unroll
                for (int p = 0; p < 2; p++) {
                    ull xx = xv[p];
                    fma2(acc[p][0], xx, bb0);
                    fma2(acc[p][1], xx, bb1);
                    fma2(acc[p][2], xx, bb2);
                }
            }
#pragma unroll
            for (int p = 0; p < 2; p++) {
                int i = i0 + 2 * p;
                float2 c0 = unpack2(acc[p][0]);   // s = lane       (Qux)
                float2 c1 = unpack2(acc[p][1]);   // s = lane + 32  (Qux)
                float2 c2 = unpack2(acc[p][2]);   // s = lane + 64  (Quu)
                float v00 = c0.x + Cb[(64 + i) * 96 + lane];
                float v10 = c0.y + Cb[(64 + i + 1) * 96 + lane];
                float v01 = c1.x + Cb[(64 + i) * 96 + lane + 32];
                float v11 = c1.y + Cb[(64 + i + 1) * 96 + lane + 32];
                float v02 = c2.x + Cb[(64 + i) * 96 + lane + 64];
                float v12 = c2.y + Cb[(64 + i + 1) * 96 + lane + 64];
                sQxS[i * 68 + lane] = v00;            sAug[i * 100 + 32 + lane] = v00;
                sQxS[(i + 1) * 68 + lane] = v10;      sAug[(i + 1) * 100 + 32 + lane] = v10;
                sQxS[i * 68 + lane + 32] = v01;       sAug[i * 100 + 64 + lane] = v01;
                sQxS[(i + 1) * 68 + lane + 32] = v11; sAug[(i + 1) * 100 + 64 + lane] = v11;
                sAug[i * 100 + lane] = v02;
                sAug[(i + 1) * 100 + lane] = v12;
            }
        }
        if (tid < 32) sAug[tid * 100 + 96] = sq[64 + tid];   // qu
        __syncthreads();

        // ---- Gauss-Jordan (unnormalized; SPD, no pivoting; 1 barrier/pivot)
        {
            int r = tid >> 3, sub = tid & 7;
            for (int kp = 0; kp < 32; kp++) {
                if (r != kp) {
                    float f = sAug[r * 100 + kp] / sAug[kp * 100 + kp];
                    for (int j = kp + 1 + sub; j <= 96; j += 8)
                        sAug[r * 100 + j] -= f * sAug[kp * 100 + j];
                }
                __syncthreads();
            }
        }

        // diag inverses, k
        if (tid < 32) {
            float di = 1.0f / sAug[tid * 100 + tid];
            sdin[tid] = di;
            float kv = -sAug[tid * 100 + 96] * di;
            skv[tid] = kv;
            g_kv[tb * NC_ + tid] = kv;
        }
        __syncthreads();

        // K = -D^{-1} Aug[:,32:96]
        {
            float* Kg = g_K + tb * NC_ * NS_;
            for (int i = tid; i < NC_ * NS_; i += 256) {
                int m = i >> 6, j = i & 63;
                float val = -sAug[m * 100 + 32 + j] * sdin[m];
                sK[m * 68 + j] = val;
                Kg[i] = val;
            }
        }
        __syncthreads();

        // ---- V_new[i][j] = C[i][j] + sum_n F[n][i] W[n][j] + sum_m Qux[m][i] K[m][j]
        {
            int i0 = w * 8;
            ull acc[4][2];
#pragma unroll
            for (int p = 0; p < 4; p++) { acc[p][0] = 0; acc[p][1] = 0; }
#pragma unroll 4
            for (int n = 0; n < 64; n++) {
                float b0 = sW[n * 100 + lane];
                float b1 = sW[n * 100 + lane + 32];
                ull bb0 = pack2(b0, b0), bb1 = pack2(b1, b1);
                const ull* xv = (const ull*)&sF[n * 100 + i0];
#pragma unroll
                for (int p = 0; p < 4; p++) {
                    ull xx = xv[p];
                    fma2(acc[p][0], xx, bb0);
                    fma2(acc[p][1], xx, bb1);
                }
            }
#pragma unroll 4
            for (int m = 0; m < 32; m++) {
                float b0 = sK[m * 68 + lane];
                float b1 = sK[m * 68 + lane + 32];
                ull bb0 = pack2(b0, b0), bb1 = pack2(b1, b1);
                const ull* xv = (const ull*)&sQxS[m * 68 + i0];
#pragma unroll
                for (int p = 0; p < 4; p++) {
                    ull xx = xv[p];
                    fma2(acc[p][0], xx, bb0);
                    fma2(acc[p][1], xx, bb1);
                }
            }
#pragma unroll
            for (int p = 0; p < 4; p++) {
                int i = i0 + 2 * p;
                float2 c0 = unpack2(acc[p][0]);
                float2 c1 = unpack2(acc[p][1]);
                sV[i * 68 + lane]            = c0.x + Cb[i * 96 + lane];
                sV[(i + 1) * 68 + lane]      = c0.y + Cb[(i + 1) * 96 + lane];
                sV[i * 68 + lane + 32]       = c1.x + Cb[i * 96 + lane + 32];
                sV[(i + 1) * 68 + lane + 32] = c1.y + Cb[(i + 1) * 96 + lane + 32];
            }
        }
        // v_new[i] = qx[i] + sum_m Qux[m][i] k[m]
        if (tid < NS_) {
            float acc = sq[tid];
#pragma unroll 4
            for (int m = 0; m < 32; m++) acc += sQxS[m * 68 + tid] * skv[m];
            sv[tid] = acc;
        }
        __syncthreads();
    }
}

// ---------------- rollout: base (alpha=0) and direction trajectories ----------------
__global__ void rollout_kernel(const float* __restrict__ x, const float* __restrict__ u,
                               const float* __restrict__ x_init, const float* __restrict__ F) {
    int b = blockIdx.x;
    int tid = threadIdx.x;   // 128
    __shared__ float sF[64 * 97];
    __shared__ float sK[32 * 65];
    __shared__ float sk[32], su[32], sxn[64];
    __shared__ float nx0[64], dx0[64], dnx[64];
    __shared__ float sz0[96], szd[96];
    __shared__ float nxn[64], dnxn[64];

    if (tid < 64) { nx0[tid] = x_init[b * 64 + tid]; dx0[tid] = 0.f; dnx[tid] = 0.f; }
    __syncthreads();

    for (int t = 0; t < T_; t++) {
        size_t tb = (size_t)t * B_ + b;
        const float* Fb = F + tb * NS_ * SZ_;
        for (int i = tid; i < NS_ * SZ_; i += 128) sF[(i / 96) * 97 + i % 96] = Fb[i];
        const float* Kg = g_K + tb * NC_ * NS_;
        for (int i = tid; i < NC_ * NS_; i += 128) sK[(i >> 6) * 65 + (i & 63)] = Kg[i];
        if (tid < NC_) { sk[tid] = g_kv[tb * NC_ + tid]; su[tid] = u[tb * NC_ + tid]; }
        int tn = (t < T_ - 1) ? t + 1 : T_ - 1;
        if (tid < NS_) sxn[tid] = x[((size_t)tn * B_ + b) * NS_ + tid];
        __syncthreads();

        // controls
        if (tid < NC_) {
            float a0 = su[tid], a1 = sk[tid];
#pragma unroll 8
            for (int n = 0; n < 64; n++) { float kk = sK[tid * 65 + n]; a0 += kk * dx0[n]; a1 += kk * dnx[n]; }
            sz0[64 + tid] = a0; szd[64 + tid] = a1;
        }
        if (tid < NS_) { sz0[tid] = nx0[tid]; szd[tid] = dnx[tid]; }
        __syncthreads();

        // record entry state+control
        if (tid < SZ_) { g_z0[tb * SZ_ + tid] = sz0[tid]; g_dz[tb * SZ_ + tid] = szd[tid]; }

        // next state
        if (tid < NS_) {
            float a0 = 0.f, a1 = 0.f;
            const float* fr = &sF[tid * 97];
#pragma unroll 8
            for (int s = 0; s < 96; s++) { float fv = fr[s]; a0 += fv * sz0[s]; a1 += fv * szd[s]; }
            nxn[tid] = a0; dnxn[tid] = a1;
        }
        __syncthreads();
        if (tid < NS_) { nx0[tid] = nxn[tid]; dx0[tid] = nxn[tid] - sxn[tid]; dnx[tid] = dnxn[tid]; }
        __syncthreads();
    }
}

// ---------------- cost quadratic coefficients: cost(a) = q0 + a q1 + a^2 q2 ----------------
__global__ void coef_kernel(const float* __restrict__ C, const float* __restrict__ c) {
    int tb = blockIdx.x;
    const float* Cb = C + (size_t)tb * SZ_ * SZ_;
    const float* cb = c + (size_t)tb * SZ_;
    __shared__ float sC[SZ_ * 97];
    __shared__ float sz[96], sd[96];
    __shared__ float r0[128], r1[128], r2[128];
    int tid = threadIdx.x;

    if (tid < SZ_) { sz[tid] = g_z0[(size_t)tb * SZ_ + tid]; sd[tid] = g_dz[(size_t)tb * SZ_ + tid]; }
    const float4* C4 = (const float4*)Cb;
    for (int i4 = tid; i4 < SZ_ * SZ_ / 4; i4 += 128) {
        float4 v = C4[i4];
        int e = i4 * 4; int r = e / SZ_; int cc = e % SZ_;
        float* dst = &sC[r * 97 + cc];
        dst[0] = v.x; dst[1] = v.y; dst[2] = v.z; dst[3] = v.w;
    }
    __syncthreads();

    float p0 = 0.f, p1 = 0.f, p2 = 0.f;
    if (tid < SZ_) {
        float y0 = 0.f, yd = 0.f;
        const float* row = &sC[tid * 97];
#pragma unroll 8
        for (int j = 0; j < SZ_; j++) { float cv = row[j]; y0 += cv * sz[j]; yd += cv * sd[j]; }
        float cv = cb[tid];
        p0 = sz[tid] * (0.5f * y0 + cv);
        p1 = sd[tid] * (y0 + cv);
        p2 = 0.5f * sd[tid] * yd;
    }
    r0[tid] = p0; r1[tid] = p1; r2[tid] = p2;
    __syncthreads();
    for (int s = 64; s > 0; s >>= 1) {
        if (tid < s) { r0[tid] += r0[tid + s]; r1[tid] += r1[tid + s]; r2[tid] += r2[tid + s]; }
        __syncthreads();
    }
    if (tid == 0) { g_q0[tb] = r0[0]; g_q1[tb] = r1[0]; g_q2[tb] = r2[0]; }
}

// ---------------- line search resolve + cost output ----------------
__global__ void ls_kernel(float* __restrict__ out_cost) {
    int b = threadIdx.x;  // 512
    float old = 0.f, A0 = 0.f, A1 = 0.f, A2 = 0.f;
    for (int t = 0; t < T_; t++) {
        int idx = t * B_ + b;
        old += g_costpart[idx];
        A0 += g_q0[idx]; A1 += g_q1[idx]; A2 += g_q2[idx];
    }
    float alpha = 1.f;
#pragma unroll
    for (int i = 0; i < 3; i++) {
        float cst = A0 + alpha * (A1 + alpha * A2);
        if (cst > old) alpha *= 0.5f;
    }
    float cur = A0 + alpha * (A1 + alpha * A2);
    g_alpha[b] = alpha;
    out_cost[b] = cur;
}

// ---------------- final outputs: new_x, new_u ----------------
__global__ void out_kernel(float* __restrict__ out) {
    size_t total = (size_t)T_ * B_ * SZ_;
    for (size_t idx = blockIdx.x * (size_t)blockDim.x + threadIdx.x; idx < total;
         idx += (size_t)gridDim.x * blockDim.x) {
        size_t tb = idx / SZ_;
        int s = (int)(idx % SZ_);
        int b = (int)(tb % B_);
        float val = g_z0[idx] + g_alpha[b] * g_dz[idx];
        if (s < NS_) out[tb * NS_ + s] = val;
        else         out[(size_t)T_ * B_ * NS_ + tb * NC_ + (s - NS_)] = val;
    }
}

// ---------------- launch ----------------
extern "C" void kernel_launch(void* const* d_in, const int* in_sizes, int n_in,
                              void* d_out, int out_size) {
    const float *x = nullptr, *u = nullptr, *xi = nullptr, *C = nullptr, *c = nullptr, *F = nullptr;
    for (int i = 0; i < n_in; i++) {
        long long s = in_sizes[i];
        const float* p = (const float*)d_in[i];
        if      (s == (long long)T_ * B_ * SZ_ * SZ_) C = p;
        else if (s == (long long)T_ * B_ * NS_ * SZ_) F = p;
        else if (s == (long long)T_ * B_ * SZ_)       c = p;
        else if (s == (long long)T_ * B_ * NS_)       x = p;
        else if (s == (long long)T_ * B_ * NC_)       u = p;
        else if (s == (long long)B_ * NS_)            xi = p;
    }
    float* out = (float*)d_out;

    cudaFuncSetAttribute(backward_kernel, cudaFuncAttributeMaxDynamicSharedMemorySize, BK_SMEM);

    prep_kernel<<<T_ * B_, 128>>>(x, u, C, c);
    backward_kernel<<<B_, 256, BK_SMEM>>>(C, F);
    rollout_kernel<<<B_, 128>>>(x, u, xi, F);
    coef_kernel<<<T_ * B_, 128>>>(C, c);
    ls_kernel<<<1, B_>>>(out + (size_t)T_ * B_ * (NS_ + NC_));
    out_kernel<<<4096, 256>>>(out);
}

// round 8
// speedup vs baseline: 1.4936x; 1.0003x over previous
#include <cuda_runtime.h>
#include <cstddef>

static constexpr int T_  = 32;
static constexpr int B_  = 512;
static constexpr int NS_ = 64;
static constexpr int NC_ = 32;
static constexpr int SZ_ = 96;   // NS + NC

using ull = unsigned long long;

// ---------------- scratch (static device globals; no allocation) ----------------
__device__ float g_cback[(size_t)T_ * B_ * SZ_];      // C@xu + c
__device__ float g_costpart[T_ * B_];                 // per (t,b) old-cost contribution
__device__ float g_q0[T_ * B_];
__device__ float g_q1[T_ * B_];
__device__ float g_q2[T_ * B_];
__device__ float g_K[(size_t)T_ * B_ * NC_ * NS_];    // gains
__device__ float g_kv[(size_t)T_ * B_ * NC_];
__device__ float g_z0[(size_t)T_ * B_ * SZ_];         // base rollout [nx;nu] (alpha=0)
__device__ float g_dz[(size_t)T_ * B_ * SZ_];         // d/dalpha of rollout
__device__ float g_alpha[B_];

// ---------------- packed f32x2 helpers ----------------
__device__ __forceinline__ void fma2(ull& acc, ull x, ull b) {
    asm("fma.rn.f32x2 %0, %1, %2, %0;" : "+l"(acc) : "l"(x), "l"(b));
}
__device__ __forceinline__ ull pack2(float lo, float hi) {
    ull r;
    asm("mov.b64 %0, {%1, %2};" : "=l"(r) : "f"(lo), "f"(hi));
    return r;
}
__device__ __forceinline__ float2 unpack2(ull v) {
    float2 r;
    asm("mov.b64 {%0, %1}, %2;" : "=f"(r.x), "=f"(r.y) : "l"(v));
    return r;
}

// ---------------- prep: c_back = C@xu + c ; old-cost partials ----------------
// C is exactly symmetric -> row dot == column dot -> coalesced column reads, no staging.
__global__ void prep_kernel(const float* __restrict__ x, const float* __restrict__ u,
                            const float* __restrict__ C, const float* __restrict__ c) {
    int tb = blockIdx.x;                 // t*B + b
    int tid = threadIdx.x;               // 96 threads, 3 warps
    __shared__ float sxu[SZ_];
    __shared__ float swp[3];

    if (tid < NS_)      sxu[tid] = x[(size_t)tb * NS_ + tid];
    else if (tid < SZ_) sxu[tid] = u[(size_t)tb * NC_ + (tid - NS_)];
    __syncthreads();

    const float* col = C + (size_t)tb * SZ_ * SZ_ + tid;
    float acc = 0.f;
#pragma unroll 8
    for (int j = 0; j < SZ_; j++) acc += col[j * SZ_] * sxu[j];
    float cv = c[(size_t)tb * SZ_ + tid];
    g_cback[(size_t)tb * SZ_ + tid] = acc + cv;
    float part = sxu[tid] * (0.5f * acc + cv);

#pragma unroll
    for (int o = 16; o > 0; o >>= 1) part += __shfl_down_sync(0xffffffffu, part, o);
    if ((tid & 31) == 0) swp[tid >> 5] = part;
    __syncthreads();
    if (tid == 0) g_costpart[tb] = swp[0] + swp[1] + swp[2];
}

// ---------------- persistent backward Riccati (one CTA per batch, loop over t) ----------------
// Region A holds V (64x66) during GEMM1, then Aug (32x104) for the solve, then V_new.
static constexpr int AUG_S  = 104;                   // 8 mod 32 -> conflict-free GJ
static constexpr int OFF_A  = 0;                     // 64x66 = 4224 (>= 32x104 = 3328)
static constexpr int A_FL   = 64 * 66;
static constexpr int OFF_W  = OFF_A  + A_FL;         // 64x96  W = V F
static constexpr int OFF_QX = OFF_W  + 64 * 96;      // 32x66  saved Qux
static constexpr int OFF_K  = OFF_QX + 32 * 66;      // 32x66
static constexpr int OFF_q  = OFF_K  + 32 * 66;      // 96
static constexpr int OFF_v  = OFF_q  + 96;           // 64
static constexpr int OFF_kv = OFF_v  + 64;           // 32
static constexpr int OFF_di = OFF_kv + 32;           // 32
static constexpr int BK_FLOATS = OFF_di + 32;
static constexpr int BK_SMEM = BK_FLOATS * 4;        // 59.3 KB -> 3 CTAs/SM

__global__ void __launch_bounds__(256, 3)
backward_kernel(const float* __restrict__ C, const float* __restrict__ F) {
    extern __shared__ float sm[];
    float* sV   = sm + OFF_A;    // stride 66
    float* sAug = sm + OFF_A;    // stride 104 (overlays V)
    float* sW   = sm + OFF_W;    // stride 96
    float* sQxS = sm + OFF_QX;   // stride 66
    float* sK   = sm + OFF_K;    // stride 66
    float* sq   = sm + OFF_q;
    float* sv   = sm + OFF_v;
    float* skv  = sm + OFF_kv;
    float* sdin = sm + OFF_di;

    int b = blockIdx.x;
    int tid = threadIdx.x, lane = tid & 31, w = tid >> 5;

    // init V = 0, v = 0
    for (int i = tid; i < A_FL; i += 256) sV[i] = 0.f;
    if (tid < NS_) sv[tid] = 0.f;
    __syncthreads();

    for (int t = T_ - 1; t >= 0; t--) {
        size_t tb = (size_t)t * B_ + b;
        const float* Cb = C + tb * SZ_ * SZ_;
        const float* Fb = F + tb * NS_ * SZ_;

        // ---- GEMM1: W[m][s] = sum_n V[m][n] F[n][s]   (F straight from global/L1)
        {
            int m0 = w * 8;
            ull acc[4][3];
#pragma unroll
            for (int p = 0; p < 4; p++) { acc[p][0] = 0; acc[p][1] = 0; acc[p][2] = 0; }
#pragma unroll 4
            for (int n = 0; n < 64; n++) {
                const float* fr = Fb + n * 96;
                float b0 = fr[lane];
                float b1 = fr[lane + 32];
                float b2 = fr[lane + 64];
                ull bb0 = pack2(b0, b0), bb1 = pack2(b1, b1), bb2 = pack2(b2, b2);
                const ull* xv = (const ull*)&sV[n * 66 + m0];
#pragma unroll
                for (int p = 0; p < 4; p++) {
                    ull xx = xv[p];
                    fma2(acc[p][0], xx, bb0);
                    fma2(acc[p][1], xx, bb1);
                    fma2(acc[p][2], xx, bb2);
                }
            }
#pragma unroll
            for (int p = 0; p < 4; p++) {
                int m = m0 + 2 * p;
                float2 c0 = unpack2(acc[p][0]);
                float2 c1 = unpack2(acc[p][1]);
                float2 c2 = unpack2(acc[p][2]);
                sW[m * 96 + lane]            = c0.x;
                sW[(m + 1) * 96 + lane]      = c0.y;
                sW[m * 96 + lane + 32]       = c1.x;
                sW[(m + 1) * 96 + lane + 32] = c1.y;
                sW[m * 96 + lane + 64]       = c2.x;
                sW[(m + 1) * 96 + lane + 64] = c2.y;
            }
        }
        // q[s] = c_back[s] + sum_n F[n][s] v[n]
        if (tid < SZ_) {
            float acc = 0.f;
#pragma unroll 8
            for (int n = 0; n < 64; n++) acc += Fb[n * 96 + tid] * sv[n];
            sq[tid] = acc + g_cback[tb * SZ_ + tid];
        }
        __syncthreads();   // V dead from here; region A becomes Aug

        // ---- GEMM2: Q-rows 64..95: C[(64+i),s] + sum_n F[n][64+i] W[n][s] -> Aug / QxSave
        {
            int i0 = w * 4;
            ull acc[2][3];
#pragma unroll
            for (int p = 0; p < 2; p++) { acc[p][0] = 0; acc[p][1] = 0; acc[p][2] = 0; }
#pragma unroll 4
            for (int n = 0; n < 64; n++) {
                float b0 = sW[n * 96 + lane];
                float b1 = sW[n * 96 + lane + 32];
                float b2 = sW[n * 96 + lane + 64];
                ull bb0 = pack2(b0, b0), bb1 = pack2(b1, b1), bb2 = pack2(b2, b2);
                const float* xp = Fb + n * 96 + 64 + i0;
#pragma unroll
                for (int p = 0; p < 2; p++) {
                    ull xx = *(const ull*)(xp + 2 * p);
                    fma2(acc[p][0], xx, bb0);
                    fma2(acc[p][1], xx, bb1);
                    fma2(acc[p][2], xx, bb2);
                }
            }
#pragma unroll
            for (int p = 0; p < 2; p++) {
                int i = i0 + 2 * p;
                float2 c0 = unpack2(acc[p][0]);   // s = lane       (Qux)
                float2 c1 = unpack2(acc[p][1]);   // s = lane + 32  (Qux)
                float2 c2 = unpack2(acc[p][2]);   // s = lane + 64  (Quu)
                float v00 = c0.x + Cb[(64 + i) * 96 + lane];
                float v10 = c0.y + Cb[(64 + i + 1) * 96 + lane];
                float v01 = c1.x + Cb[(64 + i) * 96 + lane + 32];
                float v11 = c1.y + Cb[(64 + i + 1) * 96 + lane + 32];
                float v02 = c2.x + Cb[(64 + i) * 96 + lane + 64];
                float v12 = c2.y + Cb[(64 + i + 1) * 96 + lane + 64];
                sQxS[i * 66 + lane] = v00;            sAug[i * AUG_S + 32 + lane] = v00;
                sQxS[(i + 1) * 66 + lane] = v10;      sAug[(i + 1) * AUG_S + 32 + lane] = v10;
                sQxS[i * 66 + lane + 32] = v01;       sAug[i * AUG_S + 64 + lane] = v01;
                sQxS[(i + 1) * 66 + lane + 32] = v11; sAug[(i + 1) * AUG_S + 64 + lane] = v11;
                sAug[i * AUG_S + lane] = v02;
                sAug[(i + 1) * AUG_S + lane] = v12;
            }
        }
        if (tid < 32) sAug[tid * AUG_S + 96] = sq[64 + tid];   // qu
        __syncthreads();

        // ---- Gauss-Jordan (unnormalized; SPD, no pivoting; 1 barrier/pivot)
        {
            int r = tid >> 3, sub = tid & 7;
            for (int kp = 0; kp < 32; kp++) {
                if (r != kp) {
                    float f = sAug[r * AUG_S + kp] / sAug[kp * AUG_S + kp];
                    for (int j = kp + 1 + sub; j <= 96; j += 8)
                        sAug[r * AUG_S + j] -= f * sAug[kp * AUG_S + j];
                }
                __syncthreads();
            }
        }

        // diag inverses, k
        if (tid < 32) {
            float di = 1.0f / sAug[tid * AUG_S + tid];
            sdin[tid] = di;
            float kv = -sAug[tid * AUG_S + 96] * di;
            skv[tid] = kv;
            g_kv[tb * NC_ + tid] = kv;
        }
        __syncthreads();

        // K = -D^{-1} Aug[:,32:96]
        {
            float* Kg = g_K + tb * NC_ * NS_;
            for (int i = tid; i < NC_ * NS_; i += 256) {
                int m = i >> 6, j = i & 63;
                float val = -sAug[m * AUG_S + 32 + j] * sdin[m];
                sK[m * 66 + j] = val;
                Kg[i] = val;
            }
        }
        __syncthreads();   // Aug dead from here; region A becomes V_new

        // ---- V_new[i][j] = C[i][j] + sum_n F[n][i] W[n][j] + sum_m Qux[m][i] K[m][j]
        {
            int i0 = w * 8;
            ull acc[4][2];
#pragma unroll
            for (int p = 0; p < 4; p++) { acc[p][0] = 0; acc[p][1] = 0; }
#pragma unroll 4
            for (int n = 0; n < 64; n++) {
                float b0 = sW[n * 96 + lane];
                float b1 = sW[n * 96 + lane + 32];
                ull bb0 = pack2(b0, b0), bb1 = pack2(b1, b1);
                const float* xp = Fb + n * 96 + i0;
#pragma unroll
                for (int p = 0; p < 4; p++) {
                    ull xx = *(const ull*)(xp + 2 * p);
                    fma2(acc[p][0], xx, bb0);
                    fma2(acc[p][1], xx, bb1);
                }
            }
#pragma unroll 4
            for (int m = 0; m < 32; m++) {
                float b0 = sK[m * 66 + lane];
                float b1 = sK[m * 66 + lane + 32];
                ull bb0 = pack2(b0, b0), bb1 = pack2(b1, b1);
                const ull* xv = (const ull*)&sQxS[m * 66 + i0];
#pragma unroll
                for (int p = 0; p < 4; p++) {
                    ull xx = xv[p];
                    fma2(acc[p][0], xx, bb0);
                    fma2(acc[p][1], xx, bb1);
                }
            }
            // v_new partial (needs sq/sQxS/skv; all still valid)
            float vnew = 0.f;
            if (tid < NS_) {
                float a = sq[tid];
#pragma unroll 4
                for (int m = 0; m < 32; m++) a += sQxS[m * 66 + tid] * skv[m];
                vnew = a;
            }
#pragma unroll
            for (int p = 0; p < 4; p++) {
                int i = i0 + 2 * p;
                float2 c0 = unpack2(acc[p][0]);
                float2 c1 = unpack2(acc[p][1]);
                sV[i * 66 + lane]            = c0.x + Cb[i * 96 + lane];
                sV[(i + 1) * 66 + lane]      = c0.y + Cb[(i + 1) * 96 + lane];
                sV[i * 66 + lane + 32]       = c1.x + Cb[i * 96 + lane + 32];
                sV[(i + 1) * 66 + lane + 32] = c1.y + Cb[(i + 1) * 96 + lane + 32];
            }
            if (tid < NS_) sv[tid] = vnew;
        }
        __syncthreads();
    }
}

// ---------------- rollout: base (alpha=0) and direction trajectories ----------------
__global__ void rollout_kernel(const float* __restrict__ x, const float* __restrict__ u,
                               const float* __restrict__ x_init, const float* __restrict__ F) {
    int b = blockIdx.x;
    int tid = threadIdx.x;   // 128
    __shared__ float sF[64 * 97];
    __shared__ float sK[32 * 65];
    __shared__ float sk[32], su[32], sxn[64];
    __shared__ float nx0[64], dx0[64], dnx[64];
    __shared__ float sz0[96], szd[96];
    __shared__ float nxn[64], dnxn[64];

    if (tid < 64) { nx0[tid] = x_init[b * 64 + tid]; dx0[tid] = 0.f; dnx[tid] = 0.f; }
    __syncthreads();

    for (int t = 0; t < T_; t++) {
        size_t tb = (size_t)t * B_ + b;
        const float* Fb = F + tb * NS_ * SZ_;
        const float4* F4 = (const float4*)Fb;
        for (int i4 = tid; i4 < NS_ * SZ_ / 4; i4 += 128) {
            float4 v = F4[i4];
            int e = i4 * 4; int r = e / 96; int cc = e % 96;
            float* dst = &sF[r * 97 + cc];
            dst[0] = v.x; dst[1] = v.y; dst[2] = v.z; dst[3] = v.w;
        }
        const float4* K4 = (const float4*)(g_K + tb * NC_ * NS_);
        for (int i4 = tid; i4 < NC_ * NS_ / 4; i4 += 128) {
            float4 v = K4[i4];
            int e = i4 * 4; int r = e >> 6; int cc = e & 63;
            float* dst = &sK[r * 65 + cc];
            dst[0] = v.x; dst[1] = v.y; dst[2] = v.z; dst[3] = v.w;
        }
        if (tid < NC_) { sk[tid] = g_kv[tb * NC_ + tid]; su[tid] = u[tb * NC_ + tid]; }
        int tn = (t < T_ - 1) ? t + 1 : T_ - 1;
        if (tid < NS_) sxn[tid] = x[((size_t)tn * B_ + b) * NS_ + tid];
        __syncthreads();

        // controls
        if (tid < NC_) {
            float a0 = su[tid], a1 = sk[tid];
#pragma unroll 8
            for (int n = 0; n < 64; n++) { float kk = sK[tid * 65 + n]; a0 += kk * dx0[n]; a1 += kk * dnx[n]; }
            sz0[64 + tid] = a0; szd[64 + tid] = a1;
        }
        if (tid < NS_) { sz0[tid] = nx0[tid]; szd[tid] = dnx[tid]; }
        __syncthreads();

        // record entry state+control
        if (tid < SZ_) { g_z0[tb * SZ_ + tid] = sz0[tid]; g_dz[tb * SZ_ + tid] = szd[tid]; }

        // next state
        if (tid < NS_) {
            float a0 = 0.f, a1 = 0.f;
            const float* fr = &sF[tid * 97];
#pragma unroll 8
            for (int s = 0; s < 96; s++) { float fv = fr[s]; a0 += fv * sz0[s]; a1 += fv * szd[s]; }
            nxn[tid] = a0; dnxn[tid] = a1;
        }
        __syncthreads();
        if (tid < NS_) { nx0[tid] = nxn[tid]; dx0[tid] = nxn[tid] - sxn[tid]; dnx[tid] = dnxn[tid]; }
        __syncthreads();
    }
}

// ---------------- cost quadratic coefficients: cost(a) = q0 + a q1 + a^2 q2 ----------------
// C symmetric -> coalesced column reads, no staging.
__global__ void coef_kernel(const float* __restrict__ C, const float* __restrict__ c) {
    int tb = blockIdx.x;
    int tid = threadIdx.x;   // 96 threads, 3 warps
    __shared__ float sz[SZ_], sd[SZ_];
    __shared__ float sw0[3], sw1[3], sw2[3];

    sz[tid] = g_z0[(size_t)tb * SZ_ + tid];
    sd[tid] = g_dz[(size_t)tb * SZ_ + tid];
    __syncthreads();

    const float* col = C + (size_t)tb * SZ_ * SZ_ + tid;
    float y0 = 0.f, yd = 0.f;
#pragma unroll 8
    for (int j = 0; j < SZ_; j++) {
        float cij = col[j * SZ_];
        y0 += cij * sz[j];
        yd += cij * sd[j];
    }
    float cv = c[(size_t)tb * SZ_ + tid];
    float p0 = sz[tid] * (0.5f * y0 + cv);
    float p1 = sd[tid] * (y0 + cv);
    float p2 = 0.5f * sd[tid] * yd;

#pragma unroll
    for (int o = 16; o > 0; o >>= 1) {
        p0 += __shfl_down_sync(0xffffffffu, p0, o);
        p1 += __shfl_down_sync(0xffffffffu, p1, o);
        p2 += __shfl_down_sync(0xffffffffu, p2, o);
    }
    if ((tid & 31) == 0) { int w = tid >> 5; sw0[w] = p0; sw1[w] = p1; sw2[w] = p2; }
    __syncthreads();
    if (tid == 0) {
        g_q0[tb] = sw0[0] + sw0[1] + sw0[2];
        g_q1[tb] = sw1[0] + sw1[1] + sw1[2];
        g_q2[tb] = sw2[0] + sw2[1] + sw2[2];
    }
}

// ---------------- line search resolve + cost output ----------------
__global__ void ls_kernel(float* __restrict__ out_cost) {
    int b = threadIdx.x;  // 512
    float old = 0.f, A0 = 0.f, A1 = 0.f, A2 = 0.f;
    for (int t = 0; t < T_; t++) {
        int idx = t * B_ + b;
        old += g_costpart[idx];
        A0 += g_q0[idx]; A1 += g_q1[idx]; A2 += g_q2[idx];
    }
    float alpha = 1.f;
#pragma unroll
    for (int i = 0; i < 3; i++) {
        float cst = A0 + alpha * (A1 + alpha * A2);
        if (cst > old) alpha *= 0.5f;
    }
    float cur = A0 + alpha * (A1 + alpha * A2);
    g_alpha[b] = alpha;
    out_cost[b] = cur;
}

// ---------------- final outputs: new_x, new_u ----------------
__global__ void out_kernel(float* __restrict__ out) {
    size_t total = (size_t)T_ * B_ * SZ_;
    for (size_t idx = blockIdx.x * (size_t)blockDim.x + threadIdx.x; idx < total;
         idx += (size_t)gridDim.x * blockDim.x) {
        size_t tb = idx / SZ_;
        int s = (int)(idx % SZ_);
        int b = (int)(tb % B_);
        float val = g_z0[idx] + g_alpha[b] * g_dz[idx];
        if (s < NS_) out[tb * NS_ + s] = val;
        else         out[(size_t)T_ * B_ * NS_ + tb * NC_ + (s - NS_)] = val;
    }
}

// ---------------- launch ----------------
extern "C" void kernel_launch(void* const* d_in, const int* in_sizes, int n_in,
                              void* d_out, int out_size) {
    const float *x = nullptr, *u = nullptr, *xi = nullptr, *C = nullptr, *c = nullptr, *F = nullptr;
    for (int i = 0; i < n_in; i++) {
        long long s = in_sizes[i];
        const float* p = (const float*)d_in[i];
        if      (s == (long long)T_ * B_ * SZ_ * SZ_) C = p;
        else if (s == (long long)T_ * B_ * NS_ * SZ_) F = p;
        else if (s == (long long)T_ * B_ * SZ_)       c = p;
        else if (s == (long long)T_ * B_ * NS_)       x = p;
        else if (s == (long long)T_ * B_ * NC_)       u = p;
        else if (s == (long long)B_ * NS_)            xi = p;
    }
    float* out = (float*)d_out;

    cudaFuncSetAttribute(backward_kernel, cudaFuncAttributeMaxDynamicSharedMemorySize, BK_SMEM);

    prep_kernel<<<T_ * B_, 96>>>(x, u, C, c);
    backward_kernel<<<B_, 256, BK_SMEM>>>(C, F);
    rollout_kernel<<<B_, 128>>>(x, u, xi, F);
    coef_kernel<<<T_ * B_, 96>>>(C, c);
    ls_kernel<<<1, B_>>>(out + (size_t)T_ * B_ * (NS_ + NC_));
    out_kernel<<<4096, 256>>>(out);
}

// round 9
// speedup vs baseline: 1.7986x; 1.2042x over previous
#include <cuda_runtime.h>
#include <cstddef>

static constexpr int T_  = 32;
static constexpr int B_  = 512;
static constexpr int NS_ = 64;
static constexpr int NC_ = 32;
static constexpr int SZ_ = 96;   // NS + NC

using ull = unsigned long long;

// ---------------- scratch (static device globals; no allocation) ----------------
__device__ float g_cback[(size_t)T_ * B_ * SZ_];      // C@xu + c
__device__ float g_costpart[T_ * B_];                 // per (t,b) old-cost contribution
__device__ float g_q0[T_ * B_];
__device__ float g_q1[T_ * B_];
__device__ float g_q2[T_ * B_];
__device__ float g_K[(size_t)T_ * B_ * NC_ * NS_];    // gains
__device__ float g_kv[(size_t)T_ * B_ * NC_];
__device__ float g_z0[(size_t)T_ * B_ * SZ_];         // base rollout [nx;nu] (alpha=0)
__device__ float g_dz[(size_t)T_ * B_ * SZ_];         // d/dalpha of rollout
__device__ float g_alpha[B_];

// ---------------- packed f32x2 helpers ----------------
__device__ __forceinline__ void fma2(ull& acc, ull x, ull b) {
    asm("fma.rn.f32x2 %0, %1, %2, %0;" : "+l"(acc) : "l"(x), "l"(b));
}
__device__ __forceinline__ ull pack2(float lo, float hi) {
    ull r;
    asm("mov.b64 %0, {%1, %2};" : "=l"(r) : "f"(lo), "f"(hi));
    return r;
}
__device__ __forceinline__ float2 unpack2(ull v) {
    float2 r;
    asm("mov.b64 {%0, %1}, %2;" : "=f"(r.x), "=f"(r.y) : "l"(v));
    return r;
}

// ---------------- prep: c_back = C@xu + c ; old-cost partials ----------------
// C is exactly symmetric -> row dot == column dot -> coalesced column reads, no staging.
__global__ void prep_kernel(const float* __restrict__ x, const float* __restrict__ u,
                            const float* __restrict__ C, const float* __restrict__ c) {
    int tb = blockIdx.x;                 // t*B + b
    int tid = threadIdx.x;               // 96 threads, 3 warps
    __shared__ float sxu[SZ_];
    __shared__ float swp[3];

    if (tid < NS_)      sxu[tid] = x[(size_t)tb * NS_ + tid];
    else if (tid < SZ_) sxu[tid] = u[(size_t)tb * NC_ + (tid - NS_)];
    __syncthreads();

    const float* col = C + (size_t)tb * SZ_ * SZ_ + tid;
    float acc = 0.f;
#pragma unroll 8
    for (int j = 0; j < SZ_; j++) acc += col[j * SZ_] * sxu[j];
    float cv = c[(size_t)tb * SZ_ + tid];
    g_cback[(size_t)tb * SZ_ + tid] = acc + cv;
    float part = sxu[tid] * (0.5f * acc + cv);

#pragma unroll
    for (int o = 16; o > 0; o >>= 1) part += __shfl_down_sync(0xffffffffu, part, o);
    if ((tid & 31) == 0) swp[tid >> 5] = part;
    __syncthreads();
    if (tid == 0) g_costpart[tb] = swp[0] + swp[1] + swp[2];
}

// ---------------- persistent backward Riccati (one CTA per batch, loop over t) ----------------
// Region A holds V (64x64) during GEMM1, then Aug (32x104) for the solve, then V_new.
// K is never materialized in smem: GEMM3 reads it as -din[m]*Aug[m][32+j].
static constexpr int AUG_S  = 104;                   // 8 mod 32 -> conflict-free GJ
static constexpr int OFF_A  = 0;                     // max(64*64, 32*104) = 4096
static constexpr int A_FL   = 64 * 64;
static constexpr int OFF_W  = OFF_A  + A_FL;         // 64x96  W = V F
static constexpr int OFF_QX = OFF_W  + 64 * 96;      // 32x64  saved Qux
static constexpr int OFF_q  = OFF_QX + 32 * 64;      // 64  (qx only)
static constexpr int OFF_v  = OFF_q  + 64;           // 64
static constexpr int OFF_kv = OFF_v  + 64;           // 32
static constexpr int OFF_di = OFF_kv + 32;           // 32
static constexpr int BK_FLOATS = OFF_di + 32;        // 12480
static constexpr int BK_SMEM = BK_FLOATS * 4;        // 49920 B -> 4 CTAs/SM, all 512 resident

__global__ void __launch_bounds__(256, 4)
backward_kernel(const float* __restrict__ C, const float* __restrict__ F) {
    extern __shared__ float sm[];
    float* sV   = sm + OFF_A;    // stride 64
    float* sAug = sm + OFF_A;    // stride 104 (overlays V)
    float* sW   = sm + OFF_W;    // stride 96
    float* sQxS = sm + OFF_QX;   // stride 64
    float* sq   = sm + OFF_q;    // qx
    float* sv   = sm + OFF_v;
    float* skv  = sm + OFF_kv;
    float* sdin = sm + OFF_di;

    int b = blockIdx.x;
    int tid = threadIdx.x, lane = tid & 31, w = tid >> 5;

    // init V = 0, v = 0
    for (int i = tid; i < A_FL; i += 256) sV[i] = 0.f;
    if (tid < NS_) sv[tid] = 0.f;
    __syncthreads();

    for (int t = T_ - 1; t >= 0; t--) {
        size_t tb = (size_t)t * B_ + b;
        const float* Cb = C + tb * SZ_ * SZ_;
        const float* Fb = F + tb * NS_ * SZ_;

        // ---- GEMM1: W[m][s] = sum_n V[m][n] F[n][s]   (F rows coalesced from global)
        {
            int m0 = w * 8;
            ull acc[4][3];
#pragma unroll
            for (int p = 0; p < 4; p++) { acc[p][0] = 0; acc[p][1] = 0; acc[p][2] = 0; }
#pragma unroll 4
            for (int n = 0; n < 64; n++) {
                const float* fr = Fb + n * 96;
                float b0 = fr[lane];
                float b1 = fr[lane + 32];
                float b2 = fr[lane + 64];
                ull bb0 = pack2(b0, b0), bb1 = pack2(b1, b1), bb2 = pack2(b2, b2);
                const ull* xv = (const ull*)&sV[n * 64 + m0];
#pragma unroll
                for (int p = 0; p < 4; p++) {
                    ull xx = xv[p];
                    fma2(acc[p][0], xx, bb0);
                    fma2(acc[p][1], xx, bb1);
                    fma2(acc[p][2], xx, bb2);
                }
            }
#pragma unroll
            for (int p = 0; p < 4; p++) {
                int m = m0 + 2 * p;
                float2 c0 = unpack2(acc[p][0]);
                float2 c1 = unpack2(acc[p][1]);
                float2 c2 = unpack2(acc[p][2]);
                sW[m * 96 + lane]            = c0.x;
                sW[(m + 1) * 96 + lane]      = c0.y;
                sW[m * 96 + lane + 32]       = c1.x;
                sW[(m + 1) * 96 + lane + 32] = c1.y;
                sW[m * 96 + lane + 64]       = c2.x;
                sW[(m + 1) * 96 + lane + 64] = c2.y;
            }
        }
        // q[s] = c_back[s] + sum_n F[n][s] v[n]   (qu kept in register until Aug is live)
        float rq = 0.f;
        if (tid < SZ_) {
            float acc = 0.f;
#pragma unroll 8
            for (int n = 0; n < 64; n++) acc += Fb[n * 96 + tid] * sv[n];
            rq = acc + g_cback[tb * SZ_ + tid];
            if (tid < NS_) sq[tid] = rq;
        }
        __syncthreads();   // V dead from here; region A becomes Aug
        if (tid >= NS_ && tid < SZ_) sAug[(tid - NS_) * AUG_S + 96] = rq;   // qu

        // ---- GEMM2: Q-rows 64..95: C[(64+i),s] + sum_n F[n][64+i] W[n][s] -> Aug / QxSave
        {
            int i0 = w * 4;
            ull acc[2][3];
#pragma unroll
            for (int p = 0; p < 2; p++) { acc[p][0] = 0; acc[p][1] = 0; acc[p][2] = 0; }
#pragma unroll 4
            for (int n = 0; n < 64; n++) {
                float b0 = sW[n * 96 + lane];
                float b1 = sW[n * 96 + lane + 32];
                float b2 = sW[n * 96 + lane + 64];
                ull bb0 = pack2(b0, b0), bb1 = pack2(b1, b1), bb2 = pack2(b2, b2);
                const float* xp = Fb + n * 96 + 64 + i0;
#pragma unroll
                for (int p = 0; p < 2; p++) {
                    ull xx = *(const ull*)(xp + 2 * p);
                    fma2(acc[p][0], xx, bb0);
                    fma2(acc[p][1], xx, bb1);
                    fma2(acc[p][2], xx, bb2);
                }
            }
#pragma unroll
            for (int p = 0; p < 2; p++) {
                int i = i0 + 2 * p;
                float2 c0 = unpack2(acc[p][0]);   // s = lane       (Qux)
                float2 c1 = unpack2(acc[p][1]);   // s = lane + 32  (Qux)
                float2 c2 = unpack2(acc[p][2]);   // s = lane + 64  (Quu)
                float v00 = c0.x + Cb[(64 + i) * 96 + lane];
                float v10 = c0.y + Cb[(64 + i + 1) * 96 + lane];
                float v01 = c1.x + Cb[(64 + i) * 96 + lane + 32];
                float v11 = c1.y + Cb[(64 + i + 1) * 96 + lane + 32];
                float v02 = c2.x + Cb[(64 + i) * 96 + lane + 64];
                float v12 = c2.y + Cb[(64 + i + 1) * 96 + lane + 64];
                sQxS[i * 64 + lane] = v00;            sAug[i * AUG_S + 32 + lane] = v00;
                sQxS[(i + 1) * 64 + lane] = v10;      sAug[(i + 1) * AUG_S + 32 + lane] = v10;
                sQxS[i * 64 + lane + 32] = v01;       sAug[i * AUG_S + 64 + lane] = v01;
                sQxS[(i + 1) * 64 + lane + 32] = v11; sAug[(i + 1) * AUG_S + 64 + lane] = v11;
                sAug[i * AUG_S + lane] = v02;
                sAug[(i + 1) * AUG_S + lane] = v12;
            }
        }
        __syncthreads();

        // ---- Gauss-Jordan (unnormalized; SPD, no pivoting; 1 barrier/pivot)
        {
            int r = tid >> 3, sub = tid & 7;
            for (int kp = 0; kp < 32; kp++) {
                if (r != kp) {
                    float f = sAug[r * AUG_S + kp] / sAug[kp * AUG_S + kp];
                    for (int j = kp + 1 + sub; j <= 96; j += 8)
                        sAug[r * AUG_S + j] -= f * sAug[kp * AUG_S + j];
                }
                __syncthreads();
            }
        }

        // diag inverses, k
        if (tid < 32) {
            float di = 1.0f / sAug[tid * AUG_S + tid];
            sdin[tid] = di;
            float kv = -sAug[tid * AUG_S + 96] * di;
            skv[tid] = kv;
            g_kv[tb * NC_ + tid] = kv;
        }
        __syncthreads();

        // K -> global only (smem K folded into GEMM3 reads of Aug)
        {
            float* Kg = g_K + tb * NC_ * NS_;
            for (int i = tid; i < NC_ * NS_; i += 256) {
                int m = i >> 6, j = i & 63;
                Kg[i] = -sAug[m * AUG_S + 32 + j] * sdin[m];
            }
        }

        // ---- V_new[i][j] = C[i][j] + sum_n F[n][i] W[n][j] + sum_m Qux[m][i] K[m][j]
        {
            int i0 = w * 8;
            ull acc[4][2];
#pragma unroll
            for (int p = 0; p < 4; p++) { acc[p][0] = 0; acc[p][1] = 0; }
#pragma unroll 4
            for (int n = 0; n < 64; n++) {
                float b0 = sW[n * 96 + lane];
                float b1 = sW[n * 96 + lane + 32];
                ull bb0 = pack2(b0, b0), bb1 = pack2(b1, b1);
                const float* xp = Fb + n * 96 + i0;
#pragma unroll
                for (int p = 0; p < 4; p++) {
                    ull xx = *(const ull*)(xp + 2 * p);
                    fma2(acc[p][0], xx, bb0);
                    fma2(acc[p][1], xx, bb1);
                }
            }
#pragma unroll 4
            for (int m = 0; m < 32; m++) {
                float nd = -sdin[m];
                float b0 = nd * sAug[m * AUG_S + 32 + lane];        // K[m][lane]
                float b1 = nd * sAug[m * AUG_S + 64 + lane];        // K[m][lane+32]
                ull bb0 = pack2(b0, b0), bb1 = pack2(b1, b1);
                const ull* xv = (const ull*)&sQxS[m * 64 + i0];
#pragma unroll
                for (int p = 0; p < 4; p++) {
                    ull xx = xv[p];
                    fma2(acc[p][0], xx, bb0);
                    fma2(acc[p][1], xx, bb1);
                }
            }
            // v_new partial (reads sq/sQxS/skv — outside region A)
            float vnew = 0.f;
            if (tid < NS_) {
                float a = sq[tid];
#pragma unroll 4
                for (int m = 0; m < 32; m++) a += sQxS[m * 64 + tid] * skv[m];
                vnew = a;
            }
            __syncthreads();   // ALL Aug reads complete before region A is overwritten

#pragma unroll
            for (int p = 0; p < 4; p++) {
                int i = i0 + 2 * p;
                float2 c0 = unpack2(acc[p][0]);
                float2 c1 = unpack2(acc[p][1]);
                sV[i * 64 + lane]            = c0.x + Cb[i * 96 + lane];
                sV[(i + 1) * 64 + lane]      = c0.y + Cb[(i + 1) * 96 + lane];
                sV[i * 64 + lane + 32]       = c1.x + Cb[i * 96 + lane + 32];
                sV[(i + 1) * 64 + lane + 32] = c1.y + Cb[(i + 1) * 96 + lane + 32];
            }
            if (tid < NS_) sv[tid] = vnew;
        }
        __syncthreads();
    }
}

// ---------------- rollout: base (alpha=0) and direction trajectories ----------------
__global__ void rollout_kernel(const float* __restrict__ x, const float* __restrict__ u,
                               const float* __restrict__ x_init, const float* __restrict__ F) {
    int b = blockIdx.x;
    int tid = threadIdx.x;   // 128
    __shared__ float sF[64 * 97];
    __shared__ float sK[32 * 65];
    __shared__ float sk[32], su[32], sxn[64];
    __shared__ float nx0[64], dx0[64], dnx[64];
    __shared__ float sz0[96], szd[96];
    __shared__ float nxn[64], dnxn[64];

    if (tid < 64) { nx0[tid] = x_init[b * 64 + tid]; dx0[tid] = 0.f; dnx[tid] = 0.f; }
    __syncthreads();

    for (int t = 0; t < T_; t++) {
        size_t tb = (size_t)t * B_ + b;
        const float* Fb = F + tb * NS_ * SZ_;
        const float4* F4 = (const float4*)Fb;
        for (int i4 = tid; i4 < NS_ * SZ_ / 4; i4 += 128) {
            float4 v = F4[i4];
            int e = i4 * 4; int r = e / 96; int cc = e % 96;
            float* dst = &sF[r * 97 + cc];
            dst[0] = v.x; dst[1] = v.y; dst[2] = v.z; dst[3] = v.w;
        }
        const float4* K4 = (const float4*)(g_K + tb * NC_ * NS_);
        for (int i4 = tid; i4 < NC_ * NS_ / 4; i4 += 128) {
            float4 v = K4[i4];
            int e = i4 * 4; int r = e >> 6; int cc = e & 63;
            float* dst = &sK[r * 65 + cc];
            dst[0] = v.x; dst[1] = v.y; dst[2] = v.z; dst[3] = v.w;
        }
        if (tid < NC_) { sk[tid] = g_kv[tb * NC_ + tid]; su[tid] = u[tb * NC_ + tid]; }
        int tn = (t < T_ - 1) ? t + 1 : T_ - 1;
        if (tid < NS_) sxn[tid] = x[((size_t)tn * B_ + b) * NS_ + tid];
        __syncthreads();

        // controls
        if (tid < NC_) {
            float a0 = su[tid], a1 = sk[tid];
#pragma unroll 8
            for (int n = 0; n < 64; n++) { float kk = sK[tid * 65 + n]; a0 += kk * dx0[n]; a1 += kk * dnx[n]; }
            sz0[64 + tid] = a0; szd[64 + tid] = a1;
        }
        if (tid < NS_) { sz0[tid] = nx0[tid]; szd[tid] = dnx[tid]; }
        __syncthreads();

        // record entry state+control
        if (tid < SZ_) { g_z0[tb * SZ_ + tid] = sz0[tid]; g_dz[tb * SZ_ + tid] = szd[tid]; }

        // next state
        if (tid < NS_) {
            float a0 = 0.f, a1 = 0.f;
            const float* fr = &sF[tid * 97];
#pragma unroll 8
            for (int s = 0; s < 96; s++) { float fv = fr[s]; a0 += fv * sz0[s]; a1 += fv * szd[s]; }
            nxn[tid] = a0; dnxn[tid] = a1;
        }
        __syncthreads();
        if (tid < NS_) { nx0[tid] = nxn[tid]; dx0[tid] = nxn[tid] - sxn[tid]; dnx[tid] = dnxn[tid]; }
        __syncthreads();
    }
}

// ---------------- cost quadratic coefficients: cost(a) = q0 + a q1 + a^2 q2 ----------------
// C symmetric -> coalesced column reads, no staging.
__global__ void coef_kernel(const float* __restrict__ C, const float* __restrict__ c) {
    int tb = blockIdx.x;
    int tid = threadIdx.x;   // 96 threads, 3 warps
    __shared__ float sz[SZ_], sd[SZ_];
    __shared__ float sw0[3], sw1[3], sw2[3];

    sz[tid] = g_z0[(size_t)tb * SZ_ + tid];
    sd[tid] = g_dz[(size_t)tb * SZ_ + tid];
    __syncthreads();

    const float* col = C + (size_t)tb * SZ_ * SZ_ + tid;
    float y0 = 0.f, yd = 0.f;
#pragma unroll 8
    for (int j = 0; j < SZ_; j++) {
        float cij = col[j * SZ_];
        y0 += cij * sz[j];
        yd += cij * sd[j];
    }
    float cv = c[(size_t)tb * SZ_ + tid];
    float p0 = sz[tid] * (0.5f * y0 + cv);
    float p1 = sd[tid] * (y0 + cv);
    float p2 = 0.5f * sd[tid] * yd;

#pragma unroll
    for (int o = 16; o > 0; o >>= 1) {
        p0 += __shfl_down_sync(0xffffffffu, p0, o);
        p1 += __shfl_down_sync(0xffffffffu, p1, o);
        p2 += __shfl_down_sync(0xffffffffu, p2, o);
    }
    if ((tid & 31) == 0) { int w = tid >> 5; sw0[w] = p0; sw1[w] = p1; sw2[w] = p2; }
    __syncthreads();
    if (tid == 0) {
        g_q0[tb] = sw0[0] + sw0[1] + sw0[2];
        g_q1[tb] = sw1[0] + sw1[1] + sw1[2];
        g_q2[tb] = sw2[0] + sw2[1] + sw2[2];
    }
}

// ---------------- line search resolve + cost output ----------------
__global__ void ls_kernel(float* __restrict__ out_cost) {
    int b = threadIdx.x;  // 512
    float old = 0.f, A0 = 0.f, A1 = 0.f, A2 = 0.f;
    for (int t = 0; t < T_; t++) {
        int idx = t * B_ + b;
        old += g_costpart[idx];
        A0 += g_q0[idx]; A1 += g_q1[idx]; A2 += g_q2[idx];
    }
    float alpha = 1.f;
#pragma unroll
    for (int i = 0; i < 3; i++) {
        float cst = A0 + alpha * (A1 + alpha * A2);
        if (cst > old) alpha *= 0.5f;
    }
    float cur = A0 + alpha * (A1 + alpha * A2);
    g_alpha[b] = alpha;
    out_cost[b] = cur;
}

// ---------------- final outputs: new_x, new_u ----------------
__global__ void out_kernel(float* __restrict__ out) {
    size_t total = (size_t)T_ * B_ * SZ_;
    for (size_t idx = blockIdx.x * (size_t)blockDim.x + threadIdx.x; idx < total;
         idx += (size_t)gridDim.x * blockDim.x) {
        size_t tb = idx / SZ_;
        int s = (int)(idx % SZ_);
        int b = (int)(tb % B_);
        float val = g_z0[idx] + g_alpha[b] * g_dz[idx];
        if (s < NS_) out[tb * NS_ + s] = val;
        else         out[(size_t)T_ * B_ * NS_ + tb * NC_ + (s - NS_)] = val;
    }
}

// ---------------- launch ----------------
extern "C" void kernel_launch(void* const* d_in, const int* in_sizes, int n_in,
                              void* d_out, int out_size) {
    const float *x = nullptr, *u = nullptr, *xi = nullptr, *C = nullptr, *c = nullptr, *F = nullptr;
    for (int i = 0; i < n_in; i++) {
        long long s = in_sizes[i];
        const float* p = (const float*)d_in[i];
        if      (s == (long long)T_ * B_ * SZ_ * SZ_) C = p;
        else if (s == (long long)T_ * B_ * NS_ * SZ_) F = p;
        else if (s == (long long)T_ * B_ * SZ_)       c = p;
        else if (s == (long long)T_ * B_ * NS_)       x = p;
        else if (s == (long long)T_ * B_ * NC_)       u = p;
        else if (s == (long long)B_ * NS_)            xi = p;
    }
    float* out = (float*)d_out;

    cudaFuncSetAttribute(backward_kernel, cudaFuncAttributeMaxDynamicSharedMemorySize, BK_SMEM);

    prep_kernel<<<T_ * B_, 96>>>(x, u, C, c);
    backward_kernel<<<B_, 256, BK_SMEM>>>(C, F);
    rollout_kernel<<<B_, 128>>>(x, u, xi, F);
    coef_kernel<<<T_ * B_, 96>>>(C, c);
    ls_kernel<<<1, B_>>>(out + (size_t)T_ * B_ * (NS_ + NC_));
    out_kernel<<<4096, 256>>>(out);
}

// round 10
// speedup vs baseline: 1.8423x; 1.0243x over previous
#include <cuda_runtime.h>
#include <cstddef>

static constexpr int T_  = 32;
static constexpr int B_  = 512;
static constexpr int NS_ = 64;
static constexpr int NC_ = 32;
static constexpr int SZ_ = 96;   // NS + NC

using ull = unsigned long long;

// ---------------- scratch (static device globals; no allocation) ----------------
__device__ float g_cback[(size_t)T_ * B_ * SZ_];      // C@xu + c
__device__ float g_costpart[T_ * B_];                 // per (t,b) old-cost contribution
__device__ float g_q0[T_ * B_];
__device__ float g_q1[T_ * B_];
__device__ float g_q2[T_ * B_];
__device__ float g_K[(size_t)T_ * B_ * NC_ * NS_];    // gains
__device__ float g_kv[(size_t)T_ * B_ * NC_];
__device__ float g_z0[(size_t)T_ * B_ * SZ_];         // base rollout [nx;nu] (alpha=0)
__device__ float g_dz[(size_t)T_ * B_ * SZ_];         // d/dalpha of rollout
__device__ float g_alpha[B_];

// ---------------- packed f32x2 helpers ----------------
__device__ __forceinline__ void fma2(ull& acc, ull x, ull b) {
    asm("fma.rn.f32x2 %0, %1, %2, %0;" : "+l"(acc) : "l"(x), "l"(b));
}
__device__ __forceinline__ ull pack2(float lo, float hi) {
    ull r;
    asm("mov.b64 %0, {%1, %2};" : "=l"(r) : "f"(lo), "f"(hi));
    return r;
}
__device__ __forceinline__ float2 unpack2(ull v) {
    float2 r;
    asm("mov.b64 {%0, %1}, %2;" : "=f"(r.x), "=f"(r.y) : "l"(v));
    return r;
}

// ---------------- prep: c_back = C@xu + c ; old-cost partials ----------------
// C is exactly symmetric -> row dot == column dot -> coalesced column reads, no staging.
__global__ void prep_kernel(const float* __restrict__ x, const float* __restrict__ u,
                            const float* __restrict__ C, const float* __restrict__ c) {
    int tb = blockIdx.x;                 // t*B + b
    int tid = threadIdx.x;               // 96 threads, 3 warps
    __shared__ float sxu[SZ_];
    __shared__ float swp[3];

    if (tid < NS_)      sxu[tid] = x[(size_t)tb * NS_ + tid];
    else if (tid < SZ_) sxu[tid] = u[(size_t)tb * NC_ + (tid - NS_)];
    __syncthreads();

    const float* col = C + (size_t)tb * SZ_ * SZ_ + tid;
    float acc = 0.f;
#pragma unroll 8
    for (int j = 0; j < SZ_; j++) acc += col[j * SZ_] * sxu[j];
    float cv = c[(size_t)tb * SZ_ + tid];
    g_cback[(size_t)tb * SZ_ + tid] = acc + cv;
    float part = sxu[tid] * (0.5f * acc + cv);

#pragma unroll
    for (int o = 16; o > 0; o >>= 1) part += __shfl_down_sync(0xffffffffu, part, o);
    if ((tid & 31) == 0) swp[tid >> 5] = part;
    __syncthreads();
    if (tid == 0) g_costpart[tb] = swp[0] + swp[1] + swp[2];
}

// ---------------- persistent backward Riccati (one CTA per batch, loop over t) ----------------
// Region A holds V (64x66, symmetric) during GEMM1, then Aug (32x104), then V_new.
// K never materialized in smem: GEMM3 reads it as -din[m]*Aug[m][32+j].
// GEMM3 computes only the lower triangle of V_new (pair-interleaved rows) and mirrors.
static constexpr int AUG_S  = 104;                   // 8 mod 32 -> conflict-free GJ
static constexpr int V_S    = 66;                    // even (b64 aligned), mirror 2-way conflict
static constexpr int OFF_A  = 0;                     // max(64*66, 32*104) = 4224
static constexpr int A_FL   = 64 * V_S;
static constexpr int OFF_W  = OFF_A  + A_FL;         // 64x96  W = V F
static constexpr int OFF_QX = OFF_W  + 64 * 96;      // 32x64  saved Qux
static constexpr int OFF_q  = OFF_QX + 32 * 64;      // 64  (qx only)
static constexpr int OFF_v  = OFF_q  + 64;           // 64
static constexpr int OFF_kv = OFF_v  + 64;           // 32
static constexpr int OFF_di = OFF_kv + 32;           // 32
static constexpr int BK_FLOATS = OFF_di + 32;        // 12608
static constexpr int BK_SMEM = BK_FLOATS * 4;        // 50432 B -> 4 CTAs/SM, all 512 resident

__global__ void __launch_bounds__(256, 4)
backward_kernel(const float* __restrict__ C, const float* __restrict__ F) {
    extern __shared__ float sm[];
    float* sV   = sm + OFF_A;    // stride V_S
    float* sAug = sm + OFF_A;    // stride 104 (overlays V)
    float* sW   = sm + OFF_W;    // stride 96
    float* sQxS = sm + OFF_QX;   // stride 64
    float* sq   = sm + OFF_q;    // qx
    float* sv   = sm + OFF_v;
    float* skv  = sm + OFF_kv;
    float* sdin = sm + OFF_di;

    int b = blockIdx.x;
    int tid = threadIdx.x, lane = tid & 31, w = tid >> 5;

    // init V = 0, v = 0
    for (int i = tid; i < A_FL; i += 256) sV[i] = 0.f;
    if (tid < NS_) sv[tid] = 0.f;
    __syncthreads();

    for (int t = T_ - 1; t >= 0; t--) {
        size_t tb = (size_t)t * B_ + b;
        const float* Cb = C + tb * SZ_ * SZ_;
        const float* Fb = F + tb * NS_ * SZ_;
        const bool haveV = (t != T_ - 1);   // V==0 on the first backward step

        // ---- GEMM1: W[m][s] = sum_n V[m][n] F[n][s]   (F rows coalesced from global)
        if (haveV) {
            int m0 = w * 8;
            ull acc[4][3];
#pragma unroll
            for (int p = 0; p < 4; p++) { acc[p][0] = 0; acc[p][1] = 0; acc[p][2] = 0; }
#pragma unroll 4
            for (int n = 0; n < 64; n++) {
                const float* fr = Fb + n * 96;
                float b0 = fr[lane];
                float b1 = fr[lane + 32];
                float b2 = fr[lane + 64];
                ull bb0 = pack2(b0, b0), bb1 = pack2(b1, b1), bb2 = pack2(b2, b2);
                const ull* xv = (const ull*)&sV[n * V_S + m0];
#pragma unroll
                for (int p = 0; p < 4; p++) {
                    ull xx = xv[p];
                    fma2(acc[p][0], xx, bb0);
                    fma2(acc[p][1], xx, bb1);
                    fma2(acc[p][2], xx, bb2);
                }
            }
#pragma unroll
            for (int p = 0; p < 4; p++) {
                int m = m0 + 2 * p;
                float2 c0 = unpack2(acc[p][0]);
                float2 c1 = unpack2(acc[p][1]);
                float2 c2 = unpack2(acc[p][2]);
                sW[m * 96 + lane]            = c0.x;
                sW[(m + 1) * 96 + lane]      = c0.y;
                sW[m * 96 + lane + 32]       = c1.x;
                sW[(m + 1) * 96 + lane + 32] = c1.y;
                sW[m * 96 + lane + 64]       = c2.x;
                sW[(m + 1) * 96 + lane + 64] = c2.y;
            }
        }
        // q[s] = c_back[s] + sum_n F[n][s] v[n]   (qu kept in register until Aug is live)
        float rq = 0.f;
        if (tid < SZ_) {
            float acc = 0.f;
            if (haveV) {
#pragma unroll 8
                for (int n = 0; n < 64; n++) acc += Fb[n * 96 + tid] * sv[n];
            }
            rq = acc + g_cback[tb * SZ_ + tid];
            if (tid < NS_) sq[tid] = rq;
        }
        __syncthreads();   // V dead from here; region A becomes Aug
        if (tid >= NS_ && tid < SZ_) sAug[(tid - NS_) * AUG_S + 96] = rq;   // qu

        // ---- GEMM2: Q-rows 64..95: C[(64+i),s] + sum_n F[n][64+i] W[n][s] -> Aug / QxSave
        {
            int i0 = w * 4;
            ull acc[2][3];
#pragma unroll
            for (int p = 0; p < 2; p++) { acc[p][0] = 0; acc[p][1] = 0; acc[p][2] = 0; }
            if (haveV) {
#pragma unroll 4
                for (int n = 0; n < 64; n++) {
                    float b0 = sW[n * 96 + lane];
                    float b1 = sW[n * 96 + lane + 32];
                    float b2 = sW[n * 96 + lane + 64];
                    ull bb0 = pack2(b0, b0), bb1 = pack2(b1, b1), bb2 = pack2(b2, b2);
                    const float* xp = Fb + n * 96 + 64 + i0;
#pragma unroll
                    for (int p = 0; p < 2; p++) {
                        ull xx = *(const ull*)(xp + 2 * p);
                        fma2(acc[p][0], xx, bb0);
                        fma2(acc[p][1], xx, bb1);
                        fma2(acc[p][2], xx, bb2);
                    }
                }
            }
#pragma unroll
            for (int p = 0; p < 2; p++) {
                int i = i0 + 2 * p;
                float2 c0 = unpack2(acc[p][0]);   // s = lane       (Qux)
                float2 c1 = unpack2(acc[p][1]);   // s = lane + 32  (Qux)
                float2 c2 = unpack2(acc[p][2]);   // s = lane + 64  (Quu)
                float v00 = c0.x + Cb[(64 + i) * 96 + lane];
                float v10 = c0.y + Cb[(64 + i + 1) * 96 + lane];
                float v01 = c1.x + Cb[(64 + i) * 96 + lane + 32];
                float v11 = c1.y + Cb[(64 + i + 1) * 96 + lane + 32];
                float v02 = c2.x + Cb[(64 + i) * 96 + lane + 64];
                float v12 = c2.y + Cb[(64 + i + 1) * 96 + lane + 64];
                sQxS[i * 64 + lane] = v00;            sAug[i * AUG_S + 32 + lane] = v00;
                sQxS[(i + 1) * 64 + lane] = v10;      sAug[(i + 1) * AUG_S + 32 + lane] = v10;
                sQxS[i * 64 + lane + 32] = v01;       sAug[i * AUG_S + 64 + lane] = v01;
                sQxS[(i + 1) * 64 + lane + 32] = v11; sAug[(i + 1) * AUG_S + 64 + lane] = v11;
                sAug[i * AUG_S + lane] = v02;
                sAug[(i + 1) * AUG_S + lane] = v12;
            }
        }
        __syncthreads();

        // ---- Gauss-Jordan (unnormalized; SPD, no pivoting; 1 barrier/pivot)
        {
            int r = tid >> 3, sub = tid & 7;
            for (int kp = 0; kp < 32; kp++) {
                if (r != kp) {
                    float f = __fdividef(sAug[r * AUG_S + kp], sAug[kp * AUG_S + kp]);
                    for (int j = kp + 1 + sub; j <= 96; j += 8)
                        sAug[r * AUG_S + j] -= f * sAug[kp * AUG_S + j];
                }
                __syncthreads();
            }
        }

        // diag inverses, k
        if (tid < 32) {
            float di = 1.0f / sAug[tid * AUG_S + tid];
            sdin[tid] = di;
            float kv = -sAug[tid * AUG_S + 96] * di;
            skv[tid] = kv;
            g_kv[tb * NC_ + tid] = kv;
        }
        __syncthreads();

        // K -> global only (smem K folded into GEMM3 reads of Aug)
        {
            float* Kg = g_K + tb * NC_ * NS_;
            for (int i = tid; i < NC_ * NS_; i += 256) {
                int m = i >> 6, j = i & 63;
                Kg[i] = -sAug[m * AUG_S + 32 + j] * sdin[m];
            }
        }

        // ---- V_new (symmetric): lower triangle via pair-interleaved rows, then mirror.
        // Warp w owns row-pairs q = w + 8*pp, rows (2q, 2q+1).
        // pp 0,1 (rows <= 31): col block 0 only; pp 2,3: blocks 0 and 1.
        {
            ull acc[4][2];
#pragma unroll
            for (int p = 0; p < 4; p++) { acc[p][0] = 0; acc[p][1] = 0; }
            if (haveV) {
#pragma unroll 4
                for (int n = 0; n < 64; n++) {
                    float b0 = sW[n * 96 + lane];
                    float b1 = sW[n * 96 + lane + 32];
                    ull bb0 = pack2(b0, b0), bb1 = pack2(b1, b1);
#pragma unroll
                    for (int pp = 0; pp < 4; pp++) {
                        int i0 = 2 * (w + 8 * pp);
                        ull xx = *(const ull*)(Fb + n * 96 + i0);
                        fma2(acc[pp][0], xx, bb0);
                        if (pp >= 2) fma2(acc[pp][1], xx, bb1);
                    }
                }
            }
#pragma unroll 4
            for (int m = 0; m < 32; m++) {
                float nd = -sdin[m];
                float b0 = nd * sAug[m * AUG_S + 32 + lane];        // K[m][lane]
                float b1 = nd * sAug[m * AUG_S + 64 + lane];        // K[m][lane+32]
                ull bb0 = pack2(b0, b0), bb1 = pack2(b1, b1);
#pragma unroll
                for (int pp = 0; pp < 4; pp++) {
                    int i0 = 2 * (w + 8 * pp);
                    ull xx = *(const ull*)&sQxS[m * 64 + i0];
                    fma2(acc[pp][0], xx, bb0);
                    if (pp >= 2) fma2(acc[pp][1], xx, bb1);
                }
            }
            // v_new partial (reads sq/sQxS/skv — outside region A)
            float vnew = 0.f;
            if (tid < NS_) {
                float a = sq[tid];
#pragma unroll 4
                for (int m = 0; m < 32; m++) a += sQxS[m * 64 + tid] * skv[m];
                vnew = a;
            }
            __syncthreads();   // ALL Aug reads complete before region A is overwritten

#pragma unroll
            for (int pp = 0; pp < 4; pp++) {
                int i = 2 * (w + 8 * pp);
                float2 c0 = unpack2(acc[pp][0]);
                int j = lane;
                float v0 = c0.x + Cb[i * 96 + j];
                float v1 = c0.y + Cb[(i + 1) * 96 + j];
                if (j <= i)     sV[i * V_S + j]       = v0;
                if (j <  i)     sV[j * V_S + i]       = v0;
                if (j <= i + 1) sV[(i + 1) * V_S + j] = v1;
                if (j <  i + 1) sV[j * V_S + i + 1]   = v1;
                if (pp >= 2) {
                    float2 c1 = unpack2(acc[pp][1]);
                    int j2 = lane + 32;
                    float w0 = c1.x + Cb[i * 96 + j2];
                    float w1 = c1.y + Cb[(i + 1) * 96 + j2];
                    if (j2 <= i)     sV[i * V_S + j2]       = w0;
                    if (j2 <  i)     sV[j2 * V_S + i]       = w0;
                    if (j2 <= i + 1) sV[(i + 1) * V_S + j2] = w1;
                    if (j2 <  i + 1) sV[j2 * V_S + i + 1]   = w1;
                }
            }
            if (tid < NS_) sv[tid] = vnew;
        }
        __syncthreads();
    }
}

// ---------------- rollout: base (alpha=0) and direction trajectories ----------------
__global__ void rollout_kernel(const float* __restrict__ x, const float* __restrict__ u,
                               const float* __restrict__ x_init, const float* __restrict__ F) {
    int b = blockIdx.x;
    int tid = threadIdx.x;   // 128
    __shared__ float sF[64 * 97];
    __shared__ float sK[32 * 65];
    __shared__ float sk[32], su[32], sxn[64];
    __shared__ float nx0[64], dx0[64], dnx[64];
    __shared__ float sz0[96], szd[96];
    __shared__ float nxn[64], dnxn[64];

    if (tid < 64) { nx0[tid] = x_init[b * 64 + tid]; dx0[tid] = 0.f; dnx[tid] = 0.f; }
    __syncthreads();

    for (int t = 0; t < T_; t++) {
        size_t tb = (size_t)t * B_ + b;
        const float* Fb = F + tb * NS_ * SZ_;
        const float4* F4 = (const float4*)Fb;
        for (int i4 = tid; i4 < NS_ * SZ_ / 4; i4 += 128) {
            float4 v = F4[i4];
            int e = i4 * 4; int r = e / 96; int cc = e % 96;
            float* dst = &sF[r * 97 + cc];
            dst[0] = v.x; dst[1] = v.y; dst[2] = v.z; dst[3] = v.w;
        }
        const float4* K4 = (const float4*)(g_K + tb * NC_ * NS_);
        for (int i4 = tid; i4 < NC_ * NS_ / 4; i4 += 128) {
            float4 v = K4[i4];
            int e = i4 * 4; int r = e >> 6; int cc = e & 63;
            float* dst = &sK[r * 65 + cc];
            dst[0] = v.x; dst[1] = v.y; dst[2] = v.z; dst[3] = v.w;
        }
        if (tid < NC_) { sk[tid] = g_kv[tb * NC_ + tid]; su[tid] = u[tb * NC_ + tid]; }
        int tn = (t < T_ - 1) ? t + 1 : T_ - 1;
        if (tid < NS_) sxn[tid] = x[((size_t)tn * B_ + b) * NS_ + tid];
        __syncthreads();

        // controls
        if (tid < NC_) {
            float a0 = su[tid], a1 = sk[tid];
#pragma unroll 8
            for (int n = 0; n < 64; n++) { float kk = sK[tid * 65 + n]; a0 += kk * dx0[n]; a1 += kk * dnx[n]; }
            sz0[64 + tid] = a0; szd[64 + tid] = a1;
        }
        if (tid < NS_) { sz0[tid] = nx0[tid]; szd[tid] = dnx[tid]; }
        __syncthreads();

        // record entry state+control
        if (tid < SZ_) { g_z0[tb * SZ_ + tid] = sz0[tid]; g_dz[tb * SZ_ + tid] = szd[tid]; }

        // next state
        if (tid < NS_) {
            float a0 = 0.f, a1 = 0.f;
            const float* fr = &sF[tid * 97];
#pragma unroll 8
            for (int s = 0; s < 96; s++) { float fv = fr[s]; a0 += fv * sz0[s]; a1 += fv * szd[s]; }
            nxn[tid] = a0; dnxn[tid] = a1;
        }
        __syncthreads();
        if (tid < NS_) { nx0[tid] = nxn[tid]; dx0[tid] = nxn[tid] - sxn[tid]; dnx[tid] = dnxn[tid]; }
        __syncthreads();
    }
}

// ---------------- cost quadratic coefficients: cost(a) = q0 + a q1 + a^2 q2 ----------------
// C symmetric -> coalesced column reads, no staging.
__global__ void coef_kernel(const float* __restrict__ C, const float* __restrict__ c) {
    int tb = blockIdx.x;
    int tid = threadIdx.x;   // 96 threads, 3 warps
    __shared__ float sz[SZ_], sd[SZ_];
    __shared__ float sw0[3], sw1[3], sw2[3];

    sz[tid] = g_z0[(size_t)tb * SZ_ + tid];
    sd[tid] = g_dz[(size_t)tb * SZ_ + tid];
    __syncthreads();

    const float* col = C + (size_t)tb * SZ_ * SZ_ + tid;
    float y0 = 0.f, yd = 0.f;
#pragma unroll 8
    for (int j = 0; j < SZ_; j++) {
        float cij = col[j * SZ_];
        y0 += cij * sz[j];
        yd += cij * sd[j];
    }
    float cv = c[(size_t)tb * SZ_ + tid];
    float p0 = sz[tid] * (0.5f * y0 + cv);
    float p1 = sd[tid] * (y0 + cv);
    float p2 = 0.5f * sd[tid] * yd;

#pragma unroll
    for (int o = 16; o > 0; o >>= 1) {
        p0 += __shfl_down_sync(0xffffffffu, p0, o);
        p1 += __shfl_down_sync(0xffffffffu, p1, o);
        p2 += __shfl_down_sync(0xffffffffu, p2, o);
    }
    if ((tid & 31) == 0) { int w = tid >> 5; sw0[w] = p0; sw1[w] = p1; sw2[w] = p2; }
    __syncthreads();
    if (tid == 0) {
        g_q0[tb] = sw0[0] + sw0[1] + sw0[2];
        g_q1[tb] = sw1[0] + sw1[1] + sw1[2];
        g_q2[tb] = sw2[0] + sw2[1] + sw2[2];
    }
}

// ---------------- line search resolve + cost output ----------------
__global__ void ls_kernel(float* __restrict__ out_cost) {
    int b = threadIdx.x;  // 512
    float old = 0.f, A0 = 0.f, A1 = 0.f, A2 = 0.f;
    for (int t = 0; t < T_; t++) {
        int idx = t * B_ + b;
        old += g_costpart[idx];
        A0 += g_q0[idx]; A1 += g_q1[idx]; A2 += g_q2[idx];
    }
    float alpha = 1.f;
#pragma unroll
    for (int i = 0; i < 3; i++) {
        float cst = A0 + alpha * (A1 + alpha * A2);
        if (cst > old) alpha *= 0.5f;
    }
    float cur = A0 + alpha * (A1 + alpha * A2);
    g_alpha[b] = alpha;
    out_cost[b] = cur;
}

// ---------------- final outputs: new_x, new_u ----------------
__global__ void out_kernel(float* __restrict__ out) {
    size_t total = (size_t)T_ * B_ * SZ_;
    for (size_t idx = blockIdx.x * (size_t)blockDim.x + threadIdx.x; idx < total;
         idx += (size_t)gridDim.x * blockDim.x) {
        size_t tb = idx / SZ_;
        int s = (int)(idx % SZ_);
        int b = (int)(tb % B_);
        float val = g_z0[idx] + g_alpha[b] * g_dz[idx];
        if (s < NS_) out[tb * NS_ + s] = val;
        else         out[(size_t)T_ * B_ * NS_ + tb * NC_ + (s - NS_)] = val;
    }
}

// ---------------- launch ----------------
extern "C" void kernel_launch(void* const* d_in, const int* in_sizes, int n_in,
                              void* d_out, int out_size) {
    const float *x = nullptr, *u = nullptr, *xi = nullptr, *C = nullptr, *c = nullptr, *F = nullptr;
    for (int i = 0; i < n_in; i++) {
        long long s = in_sizes[i];
        const float* p = (const float*)d_in[i];
        if      (s == (long long)T_ * B_ * SZ_ * SZ_) C = p;
        else if (s == (long long)T_ * B_ * NS_ * SZ_) F = p;
        else if (s == (long long)T_ * B_ * SZ_)       c = p;
        else if (s == (long long)T_ * B_ * NS_)       x = p;
        else if (s == (long long)T_ * B_ * NC_)       u = p;
        else if (s == (long long)B_ * NS_)            xi = p;
    }
    float* out = (float*)d_out;

    cudaFuncSetAttribute(backward_kernel, cudaFuncAttributeMaxDynamicSharedMemorySize, BK_SMEM);

    prep_kernel<<<T_ * B_, 96>>>(x, u, C, c);
    backward_kernel<<<B_, 256, BK_SMEM>>>(C, F);
    rollout_kernel<<<B_, 128>>>(x, u, xi, F);
    coef_kernel<<<T_ * B_, 96>>>(C, c);
    ls_kernel<<<1, B_>>>(out + (size_t)T_ * B_ * (NS_ + NC_));
    out_kernel<<<4096, 256>>>(out);
}

// round 11
// speedup vs baseline: 2.1076x; 1.1440x over previous
#include <cuda_runtime.h>
#include <cstddef>

static constexpr int T_  = 32;
static constexpr int B_  = 512;
static constexpr int NS_ = 64;
static constexpr int NC_ = 32;
static constexpr int SZ_ = 96;   // NS + NC

using ull = unsigned long long;

// ---------------- scratch (static device globals; no allocation) ----------------
__device__ float g_cback[(size_t)T_ * B_ * SZ_];      // C@xu + c
__device__ float g_costpart[T_ * B_];                 // per (t,b) old-cost contribution
__device__ float g_q0[T_ * B_];
__device__ float g_q1[T_ * B_];
__device__ float g_q2[T_ * B_];
__device__ float g_K[(size_t)T_ * B_ * NC_ * NS_];    // gains
__device__ float g_kv[(size_t)T_ * B_ * NC_];
__device__ float g_z0[(size_t)T_ * B_ * SZ_];         // base rollout [nx;nu] (alpha=0)
__device__ float g_dz[(size_t)T_ * B_ * SZ_];         // d/dalpha of rollout
__device__ float g_alpha[B_];

// ---------------- packed f32x2 helpers ----------------
__device__ __forceinline__ void fma2(ull& acc, ull x, ull b) {
    asm("fma.rn.f32x2 %0, %1, %2, %0;" : "+l"(acc) : "l"(x), "l"(b));
}
__device__ __forceinline__ ull pack2(float lo, float hi) {
    ull r;
    asm("mov.b64 %0, {%1, %2};" : "=l"(r) : "f"(lo), "f"(hi));
    return r;
}
__device__ __forceinline__ float2 unpack2(ull v) {
    float2 r;
    asm("mov.b64 {%0, %1}, %2;" : "=f"(r.x), "=f"(r.y) : "l"(v));
    return r;
}

// ---------------- prep: c_back = C@xu + c ; old-cost partials ----------------
__global__ void prep_kernel(const float* __restrict__ x, const float* __restrict__ u,
                            const float* __restrict__ C, const float* __restrict__ c) {
    int tb = blockIdx.x;                 // t*B + b
    int tid = threadIdx.x;               // 96 threads, 3 warps
    __shared__ float sxu[SZ_];
    __shared__ float swp[3];

    if (tid < NS_)      sxu[tid] = x[(size_t)tb * NS_ + tid];
    else if (tid < SZ_) sxu[tid] = u[(size_t)tb * NC_ + (tid - NS_)];
    __syncthreads();

    const float* col = C + (size_t)tb * SZ_ * SZ_ + tid;
    float acc = 0.f;
#pragma unroll 8
    for (int j = 0; j < SZ_; j++) acc += col[j * SZ_] * sxu[j];
    float cv = c[(size_t)tb * SZ_ + tid];
    g_cback[(size_t)tb * SZ_ + tid] = acc + cv;
    float part = sxu[tid] * (0.5f * acc + cv);

#pragma unroll
    for (int o = 16; o > 0; o >>= 1) part += __shfl_down_sync(0xffffffffu, part, o);
    if ((tid & 31) == 0) swp[tid >> 5] = part;
    __syncthreads();
    if (tid == 0) g_costpart[tb] = swp[0] + swp[1] + swp[2];
}

// ---------------- persistent backward Riccati (one CTA per batch, loop over t) ----------------
// Region A holds V (64x66, symmetric) during GEMM1, then Aug (32x104), then V_new.
// F accessed through a rolling 16-row smem chunk (sFc) -> LDS instead of L2-latency LDG.
// GEMM2 + Qxx(FtW) fused into one F pass; Qxx triangle held in registers across GJ.
static constexpr int AUG_S  = 104;                   // 8 mod 32 -> conflict-free GJ
static constexpr int V_S    = 66;                    // even (b64 aligned), mirror 2-way conflict
static constexpr int OFF_A  = 0;                     // max(64*66, 32*104) = 4224
static constexpr int A_FL   = 64 * V_S;
static constexpr int OFF_W  = OFF_A  + A_FL;         // 64x96  W = V F
static constexpr int OFF_QX = OFF_W  + 64 * 96;      // 32x64  saved Qux
static constexpr int OFF_q  = OFF_QX + 32 * 64;      // 64  (qx only)
static constexpr int OFF_v  = OFF_q  + 64;           // 64
static constexpr int OFF_kv = OFF_v  + 64;           // 32
static constexpr int OFF_di = OFF_kv + 32;           // 32
static constexpr int OFF_FC = OFF_di + 32;           // 16x96 rolling F chunk
static constexpr int BK_FLOATS = OFF_FC + 16 * 96;   // 14144
static constexpr int BK_SMEM = BK_FLOATS * 4;        // 56576 B -> 4 CTAs/SM

__global__ void __launch_bounds__(256, 4)
backward_kernel(const float* __restrict__ C, const float* __restrict__ F) {
    extern __shared__ float sm[];
    float* sV   = sm + OFF_A;    // stride V_S
    float* sAug = sm + OFF_A;    // stride 104 (overlays V)
    float* sW   = sm + OFF_W;    // stride 96
    float* sQxS = sm + OFF_QX;   // stride 64
    float* sq   = sm + OFF_q;    // qx
    float* sv   = sm + OFF_v;
    float* skv  = sm + OFF_kv;
    float* sdin = sm + OFF_di;
    float* sFc  = sm + OFF_FC;   // 16x96 chunk

    int b = blockIdx.x;
    int tid = threadIdx.x, lane = tid & 31, w = tid >> 5;

    // init V = 0, v = 0
    for (int i = tid; i < A_FL; i += 256) sV[i] = 0.f;
    if (tid < NS_) sv[tid] = 0.f;
    __syncthreads();

    for (int t = T_ - 1; t >= 0; t--) {
        size_t tb = (size_t)t * B_ + b;
        const float* Cb = C + tb * SZ_ * SZ_;
        const float* Fb = F + tb * NS_ * SZ_;
        const bool haveV = (t != T_ - 1);   // V==0 on the first backward step

        // ---- Phase A: W = V F (chunked F) + q accumulation
        float qacc = 0.f;
        {
            int m0 = w * 8;
            ull acc[4][3];
#pragma unroll
            for (int p = 0; p < 4; p++) { acc[p][0] = 0; acc[p][1] = 0; acc[p][2] = 0; }
            if (haveV) {
                for (int ch = 0; ch < 4; ch++) {
                    const float4* src = (const float4*)(Fb + ch * 16 * 96);
                    for (int i = tid; i < 384; i += 256) ((float4*)sFc)[i] = src[i];
                    __syncthreads();
#pragma unroll 4
                    for (int nn = 0; nn < 16; nn++) {
                        int n = ch * 16 + nn;
                        const float* fr = sFc + nn * 96;
                        float b0 = fr[lane];
                        float b1 = fr[lane + 32];
                        float b2 = fr[lane + 64];
                        ull bb0 = pack2(b0, b0), bb1 = pack2(b1, b1), bb2 = pack2(b2, b2);
                        const ull* xv = (const ull*)&sV[n * V_S + m0];
#pragma unroll
                        for (int p = 0; p < 4; p++) {
                            ull xx = xv[p];
                            fma2(acc[p][0], xx, bb0);
                            fma2(acc[p][1], xx, bb1);
                            fma2(acc[p][2], xx, bb2);
                        }
                        if (tid < SZ_) qacc += fr[tid] * sv[n];
                    }
                    __syncthreads();
                }
                // write W
#pragma unroll
                for (int p = 0; p < 4; p++) {
                    int m = m0 + 2 * p;
                    float2 c0 = unpack2(acc[p][0]);
                    float2 c1 = unpack2(acc[p][1]);
                    float2 c2 = unpack2(acc[p][2]);
                    sW[m * 96 + lane]            = c0.x;
                    sW[(m + 1) * 96 + lane]      = c0.y;
                    sW[m * 96 + lane + 32]       = c1.x;
                    sW[(m + 1) * 96 + lane + 32] = c1.y;
                    sW[m * 96 + lane + 64]       = c2.x;
                    sW[(m + 1) * 96 + lane + 64] = c2.y;
                }
            }
        }
        float rq = 0.f;
        if (tid < SZ_) {
            rq = qacc + g_cback[tb * SZ_ + tid];
            if (tid < NS_) sq[tid] = rq;
        }
        __syncthreads();   // V dead; W visible; region A becomes Aug
        if (tid >= NS_ && tid < SZ_) sAug[(tid - NS_) * AUG_S + 96] = rq;   // qu

        // ---- Phase B (fused): Q = C + F^T W for ALL 96 rows in one F pass.
        // Rows 64..95 -> Aug/QxS now; rows 0..63 triangle -> registers (accx) across GJ.
        int i0 = w * 4;
        ull accx[4][2];
#pragma unroll
        for (int p = 0; p < 4; p++) { accx[p][0] = 0; accx[p][1] = 0; }
        {
            ull acc2[2][3];
#pragma unroll
            for (int p = 0; p < 2; p++) { acc2[p][0] = 0; acc2[p][1] = 0; acc2[p][2] = 0; }
            if (haveV) {
                for (int ch = 0; ch < 4; ch++) {
                    const float4* src = (const float4*)(Fb + ch * 16 * 96);
                    for (int i = tid; i < 384; i += 256) ((float4*)sFc)[i] = src[i];
                    __syncthreads();
#pragma unroll 4
                    for (int nn = 0; nn < 16; nn++) {
                        int n = ch * 16 + nn;
                        const float* wr = sW + n * 96;
                        float b0 = wr[lane];
                        float b1 = wr[lane + 32];
                        float b2 = wr[lane + 64];
                        ull bb0 = pack2(b0, b0), bb1 = pack2(b1, b1), bb2 = pack2(b2, b2);
                        const float* fc = sFc + nn * 96;
                        ull xa0 = *(const ull*)(fc + 64 + i0);
                        ull xa1 = *(const ull*)(fc + 64 + i0 + 2);
                        fma2(acc2[0][0], xa0, bb0); fma2(acc2[0][1], xa0, bb1); fma2(acc2[0][2], xa0, bb2);
                        fma2(acc2[1][0], xa1, bb0); fma2(acc2[1][1], xa1, bb1); fma2(acc2[1][2], xa1, bb2);
#pragma unroll
                        for (int pp = 0; pp < 4; pp++) {
                            ull xx = *(const ull*)(fc + 2 * (w + 8 * pp));
                            fma2(accx[pp][0], xx, bb0);
                            if (pp >= 2) fma2(accx[pp][1], xx, bb1);
                        }
                    }
                    __syncthreads();
                }
            }
            // GEMM2 epilogue -> Aug / QxS (+ C rows 64..95)
#pragma unroll
            for (int p = 0; p < 2; p++) {
                int i = i0 + 2 * p;
                float2 c0 = unpack2(acc2[p][0]);   // s = lane       (Qux)
                float2 c1 = unpack2(acc2[p][1]);   // s = lane + 32  (Qux)
                float2 c2 = unpack2(acc2[p][2]);   // s = lane + 64  (Quu)
                float v00 = c0.x + Cb[(64 + i) * 96 + lane];
                float v10 = c0.y + Cb[(64 + i + 1) * 96 + lane];
                float v01 = c1.x + Cb[(64 + i) * 96 + lane + 32];
                float v11 = c1.y + Cb[(64 + i + 1) * 96 + lane + 32];
                float v02 = c2.x + Cb[(64 + i) * 96 + lane + 64];
                float v12 = c2.y + Cb[(64 + i + 1) * 96 + lane + 64];
                sQxS[i * 64 + lane] = v00;            sAug[i * AUG_S + 32 + lane] = v00;
                sQxS[(i + 1) * 64 + lane] = v10;      sAug[(i + 1) * AUG_S + 32 + lane] = v10;
                sQxS[i * 64 + lane + 32] = v01;       sAug[i * AUG_S + 64 + lane] = v01;
                sQxS[(i + 1) * 64 + lane + 32] = v11; sAug[(i + 1) * AUG_S + 64 + lane] = v11;
                sAug[i * AUG_S + lane] = v02;
                sAug[(i + 1) * AUG_S + lane] = v12;
            }
        }
        __syncthreads();

        // ---- Gauss-Jordan (unnormalized; SPD, no pivoting; 1 barrier/pivot)
        {
            int r = tid >> 3, sub = tid & 7;
            for (int kp = 0; kp < 32; kp++) {
                if (r != kp) {
                    float f = __fdividef(sAug[r * AUG_S + kp], sAug[kp * AUG_S + kp]);
                    for (int j = kp + 1 + sub; j <= 96; j += 8)
                        sAug[r * AUG_S + j] -= f * sAug[kp * AUG_S + j];
                }
                __syncthreads();
            }
        }

        // diag inverses, k
        if (tid < 32) {
            float di = 1.0f / sAug[tid * AUG_S + tid];
            sdin[tid] = di;
            float kv = -sAug[tid * AUG_S + 96] * di;
            skv[tid] = kv;
            g_kv[tb * NC_ + tid] = kv;
        }
        __syncthreads();

        // K -> global only (smem K folded into V_new reads of Aug)
        {
            float* Kg = g_K + tb * NC_ * NS_;
            for (int i = tid; i < NC_ * NS_; i += 256) {
                int m = i >> 6, j = i & 63;
                Kg[i] = -sAug[m * AUG_S + 32 + j] * sdin[m];
            }
        }

        // ---- V_new finalize: accx += Qux^T K; add C; mirror-store lower triangle.
        {
#pragma unroll 4
            for (int m = 0; m < 32; m++) {
                float nd = -sdin[m];
                float b0 = nd * sAug[m * AUG_S + 32 + lane];        // K[m][lane]
                float b1 = nd * sAug[m * AUG_S + 64 + lane];        // K[m][lane+32]
                ull bb0 = pack2(b0, b0), bb1 = pack2(b1, b1);
#pragma unroll
                for (int pp = 0; pp < 4; pp++) {
                    ull xx = *(const ull*)&sQxS[m * 64 + 2 * (w + 8 * pp)];
                    fma2(accx[pp][0], xx, bb0);
                    if (pp >= 2) fma2(accx[pp][1], xx, bb1);
                }
            }
            // v_new partial (reads sq/sQxS/skv — outside region A)
            float vnew = 0.f;
            if (tid < NS_) {
                float a = sq[tid];
#pragma unroll 4
                for (int m = 0; m < 32; m++) a += sQxS[m * 64 + tid] * skv[m];
                vnew = a;
            }
            // add C (LDGs issued before the barrier so latency overlaps the wait)
            float sv0[4], sv1[4], sw0v[2], sw1v[2];
#pragma unroll
            for (int pp = 0; pp < 4; pp++) {
                int i = 2 * (w + 8 * pp);
                float2 c0 = unpack2(accx[pp][0]);
                sv0[pp] = c0.x + Cb[i * 96 + lane];
                sv1[pp] = c0.y + Cb[(i + 1) * 96 + lane];
                if (pp >= 2) {
                    float2 c1 = unpack2(accx[pp][1]);
                    sw0v[pp - 2] = c1.x + Cb[i * 96 + lane + 32];
                    sw1v[pp - 2] = c1.y + Cb[(i + 1) * 96 + lane + 32];
                }
            }
            __syncthreads();   // ALL Aug reads complete before region A is overwritten

#pragma unroll
            for (int pp = 0; pp < 4; pp++) {
                int i = 2 * (w + 8 * pp);
                int j = lane;
                if (j <= i)     sV[i * V_S + j]       = sv0[pp];
                if (j <  i)     sV[j * V_S + i]       = sv0[pp];
                if (j <= i + 1) sV[(i + 1) * V_S + j] = sv1[pp];
                if (j <  i + 1) sV[j * V_S + i + 1]   = sv1[pp];
                if (pp >= 2) {
                    int j2 = lane + 32;
                    if (j2 <= i)     sV[i * V_S + j2]       = sw0v[pp - 2];
                    if (j2 <  i)     sV[j2 * V_S + i]       = sw0v[pp - 2];
                    if (j2 <= i + 1) sV[(i + 1) * V_S + j2] = sw1v[pp - 2];
                    if (j2 <  i + 1) sV[j2 * V_S + i + 1]   = sw1v[pp - 2];
                }
            }
            if (tid < NS_) sv[tid] = vnew;
        }
        __syncthreads();
    }
}

// ---------------- rollout: base (alpha=0) and direction trajectories ----------------
__global__ void rollout_kernel(const float* __restrict__ x, const float* __restrict__ u,
                               const float* __restrict__ x_init, const float* __restrict__ F) {
    int b = blockIdx.x;
    int tid = threadIdx.x;   // 128
    __shared__ float sF[64 * 97];
    __shared__ float sK[32 * 65];
    __shared__ float sk[32], su[32], sxn[64];
    __shared__ float nx0[64], dx0[64], dnx[64];
    __shared__ float sz0[96], szd[96];
    __shared__ float nxn[64], dnxn[64];

    if (tid < 64) { nx0[tid] = x_init[b * 64 + tid]; dx0[tid] = 0.f; dnx[tid] = 0.f; }
    __syncthreads();

    for (int t = 0; t < T_; t++) {
        size_t tb = (size_t)t * B_ + b;
        const float* Fb = F + tb * NS_ * SZ_;
        const float4* F4 = (const float4*)Fb;
        for (int i4 = tid; i4 < NS_ * SZ_ / 4; i4 += 128) {
            float4 v = F4[i4];
            int e = i4 * 4; int r = e / 96; int cc = e % 96;
            float* dst = &sF[r * 97 + cc];
            dst[0] = v.x; dst[1] = v.y; dst[2] = v.z; dst[3] = v.w;
        }
        const float4* K4 = (const float4*)(g_K + tb * NC_ * NS_);
        for (int i4 = tid; i4 < NC_ * NS_ / 4; i4 += 128) {
            float4 v = K4[i4];
            int e = i4 * 4; int r = e >> 6; int cc = e & 63;
            float* dst = &sK[r * 65 + cc];
            dst[0] = v.x; dst[1] = v.y; dst[2] = v.z; dst[3] = v.w;
        }
        if (tid < NC_) { sk[tid] = g_kv[tb * NC_ + tid]; su[tid] = u[tb * NC_ + tid]; }
        int tn = (t < T_ - 1) ? t + 1 : T_ - 1;
        if (tid < NS_) sxn[tid] = x[((size_t)tn * B_ + b) * NS_ + tid];
        __syncthreads();

        // controls
        if (tid < NC_) {
            float a0 = su[tid], a1 = sk[tid];
#pragma unroll 8
            for (int n = 0; n < 64; n++) { float kk = sK[tid * 65 + n]; a0 += kk * dx0[n]; a1 += kk * dnx[n]; }
            sz0[64 + tid] = a0; szd[64 + tid] = a1;
        }
        if (tid < NS_) { sz0[tid] = nx0[tid]; szd[tid] = dnx[tid]; }
        __syncthreads();

        // record entry state+control
        if (tid < SZ_) { g_z0[tb * SZ_ + tid] = sz0[tid]; g_dz[tb * SZ_ + tid] = szd[tid]; }

        // next state
        if (tid < NS_) {
            float a0 = 0.f, a1 = 0.f;
            const float* fr = &sF[tid * 97];
#pragma unroll 8
            for (int s = 0; s < 96; s++) { float fv = fr[s]; a0 += fv * sz0[s]; a1 += fv * szd[s]; }
            nxn[tid] = a0; dnxn[tid] = a1;
        }
        __syncthreads();
        if (tid < NS_) { nx0[tid] = nxn[tid]; dx0[tid] = nxn[tid] - sxn[tid]; dnx[tid] = dnxn[tid]; }
        __syncthreads();
    }
}

// ---------------- cost quadratic coefficients: cost(a) = q0 + a q1 + a^2 q2 ----------------
__global__ void coef_kernel(const float* __restrict__ C, const float* __restrict__ c) {
    int tb = blockIdx.x;
    int tid = threadIdx.x;   // 96 threads, 3 warps
    __shared__ float sz[SZ_], sd[SZ_];
    __shared__ float sw0[3], sw1[3], sw2[3];

    sz[tid] = g_z0[(size_t)tb * SZ_ + tid];
    sd[tid] = g_dz[(size_t)tb * SZ_ + tid];
    __syncthreads();

    const float* col = C + (size_t)tb * SZ_ * SZ_ + tid;
    float y0 = 0.f, yd = 0.f;
#pragma unroll 8
    for (int j = 0; j < SZ_; j++) {
        float cij = col[j * SZ_];
        y0 += cij * sz[j];
        yd += cij * sd[j];
    }
    float cv = c[(size_t)tb * SZ_ + tid];
    float p0 = sz[tid] * (0.5f * y0 + cv);
    float p1 = sd[tid] * (y0 + cv);
    float p2 = 0.5f * sd[tid] * yd;

#pragma unroll
    for (int o = 16; o > 0; o >>= 1) {
        p0 += __shfl_down_sync(0xffffffffu, p0, o);
        p1 += __shfl_down_sync(0xffffffffu, p1, o);
        p2 += __shfl_down_sync(0xffffffffu, p2, o);
    }
    if ((tid & 31) == 0) { int w = tid >> 5; sw0[w] = p0; sw1[w] = p1; sw2[w] = p2; }
    __syncthreads();
    if (tid == 0) {
        g_q0[tb] = sw0[0] + sw0[1] + sw0[2];
        g_q1[tb] = sw1[0] + sw1[1] + sw1[2];
        g_q2[tb] = sw2[0] + sw2[1] + sw2[2];
    }
}

// ---------------- line search resolve + cost output ----------------
__global__ void ls_kernel(float* __restrict__ out_cost) {
    int b = threadIdx.x;  // 512
    float old = 0.f, A0 = 0.f, A1 = 0.f, A2 = 0.f;
    for (int t = 0; t < T_; t++) {
        int idx = t * B_ + b;
        old += g_costpart[idx];
        A0 += g_q0[idx]; A1 += g_q1[idx]; A2 += g_q2[idx];
    }
    float alpha = 1.f;
#pragma unroll
    for (int i = 0; i < 3; i++) {
        float cst = A0 + alpha * (A1 + alpha * A2);
        if (cst > old) alpha *= 0.5f;
    }
    float cur = A0 + alpha * (A1 + alpha * A2);
    g_alpha[b] = alpha;
    out_cost[b] = cur;
}

// ---------------- final outputs: new_x, new_u ----------------
__global__ void out_kernel(float* __restrict__ out) {
    size_t total = (size_t)T_ * B_ * SZ_;
    for (size_t idx = blockIdx.x * (size_t)blockDim.x + threadIdx.x; idx < total;
         idx += (size_t)gridDim.x * blockDim.x) {
        size_t tb = idx / SZ_;
        int s = (int)(idx % SZ_);
        int b = (int)(tb % B_);
        float val = g_z0[idx] + g_alpha[b] * g_dz[idx];
        if (s < NS_) out[tb * NS_ + s] = val;
        else         out[(size_t)T_ * B_ * NS_ + tb * NC_ + (s - NS_)] = val;
    }
}

// ---------------- launch ----------------
extern "C" void kernel_launch(void* const* d_in, const int* in_sizes, int n_in,
                              void* d_out, int out_size) {
    const float *x = nullptr, *u = nullptr, *xi = nullptr, *C = nullptr, *c = nullptr, *F = nullptr;
    for (int i = 0; i < n_in; i++) {
        long long s = in_sizes[i];
        const float* p = (const float*)d_in[i];
        if      (s == (long long)T_ * B_ * SZ_ * SZ_) C = p;
        else if (s == (long long)T_ * B_ * NS_ * SZ_) F = p;
        else if (s == (long long)T_ * B_ * SZ_)       c = p;
        else if (s == (long long)T_ * B_ * NS_)       x = p;
        else if (s == (long long)T_ * B_ * NC_)       u = p;
        else if (s == (long long)B_ * NS_)            xi = p;
    }
    float* out = (float*)d_out;

    cudaFuncSetAttribute(backward_kernel, cudaFuncAttributeMaxDynamicSharedMemorySize, BK_SMEM);

    prep_kernel<<<T_ * B_, 96>>>(x, u, C, c);
    backward_kernel<<<B_, 256, BK_SMEM>>>(C, F);
    rollout_kernel<<<B_, 128>>>(x, u, xi, F);
    coef_kernel<<<T_ * B_, 96>>>(C, c);
    ls_kernel<<<1, B_>>>(out + (size_t)T_ * B_ * (NS_ + NC_));
    out_kernel<<<4096, 256>>>(out);
}

// round 13
// speedup vs baseline: 2.1755x; 1.0322x over previous
#include <cuda_runtime.h>
#include <cstddef>

static constexpr int T_  = 32;
static constexpr int B_  = 512;
static constexpr int NS_ = 64;
static constexpr int NC_ = 32;
static constexpr int SZ_ = 96;   // NS + NC

using ull = unsigned long long;

// ---------------- scratch (static device globals; no allocation) ----------------
__device__ float g_cback[(size_t)T_ * B_ * SZ_];      // C@xu + c
__device__ float g_costpart[T_ * B_];                 // per (t,b) old-cost contribution
__device__ float g_q0[T_ * B_];
__device__ float g_q1[T_ * B_];
__device__ float g_q2[T_ * B_];
__device__ float g_K[(size_t)T_ * B_ * NC_ * NS_];    // gains
__device__ float g_kv[(size_t)T_ * B_ * NC_];
__device__ float g_z0[(size_t)T_ * B_ * SZ_];         // base rollout [nx;nu] (alpha=0)
__device__ float g_dz[(size_t)T_ * B_ * SZ_];         // d/dalpha of rollout
__device__ float g_alpha[B_];

// ---------------- packed f32x2 helpers ----------------
__device__ __forceinline__ void fma2(ull& acc, ull x, ull b) {
    asm("fma.rn.f32x2 %0, %1, %2, %0;" : "+l"(acc) : "l"(x), "l"(b));
}
__device__ __forceinline__ ull pack2(float lo, float hi) {
    ull r;
    asm("mov.b64 %0, {%1, %2};" : "=l"(r) : "f"(lo), "f"(hi));
    return r;
}
__device__ __forceinline__ float2 unpack2(ull v) {
    float2 r;
    asm("mov.b64 {%0, %1}, %2;" : "=f"(r.x), "=f"(r.y) : "l"(v));
    return r;
}

// ---------------- cp.async helpers ----------------
__device__ __forceinline__ void cp_async16(unsigned saddr, const float* g) {
    asm volatile("cp.async.cg.shared.global [%0], [%1], 16;" :: "r"(saddr), "l"(g));
}
__device__ __forceinline__ void cp_commit() {
    asm volatile("cp.async.commit_group;" ::: "memory");
}
__device__ __forceinline__ void cp_wait0() {
    asm volatile("cp.async.wait_group 0;" ::: "memory");
}

// ---------------- prep: c_back = C@xu + c ; old-cost partials ----------------
__global__ void prep_kernel(const float* __restrict__ x, const float* __restrict__ u,
                            const float* __restrict__ C, const float* __restrict__ c) {
    int tb = blockIdx.x;                 // t*B + b
    int tid = threadIdx.x;               // 96 threads, 3 warps
    __shared__ float sxu[SZ_];
    __shared__ float swp[3];

    if (tid < NS_)      sxu[tid] = x[(size_t)tb * NS_ + tid];
    else if (tid < SZ_) sxu[tid] = u[(size_t)tb * NC_ + (tid - NS_)];
    __syncthreads();

    const float* col = C + (size_t)tb * SZ_ * SZ_ + tid;
    float acc = 0.f;
#pragma unroll 8
    for (int j = 0; j < SZ_; j++) acc += col[j * SZ_] * sxu[j];
    float cv = c[(size_t)tb * SZ_ + tid];
    g_cback[(size_t)tb * SZ_ + tid] = acc + cv;
    float part = sxu[tid] * (0.5f * acc + cv);

#pragma unroll
    for (int o = 16; o > 0; o >>= 1) part += __shfl_down_sync(0xffffffffu, part, o);
    if ((tid & 31) == 0) swp[tid >> 5] = part;
    __syncthreads();
    if (tid == 0) g_costpart[tb] = swp[0] + swp[1] + swp[2];
}

// ---------------- persistent backward Riccati (one CTA per batch, loop over t) ----------------
// Region A holds V (64x66, symmetric) during GEMM1, then Aug (32x104), then V_new.
// F streamed through a DOUBLE-BUFFERED cp.async pipeline of 8-row chunks (2 x 3KB).
// GEMM2 + Qxx(FtW) fused into one F pass; Qxx triangle held in registers across GJ.
static constexpr int AUG_S  = 104;                   // 8 mod 32 -> conflict-free GJ
static constexpr int V_S    = 66;                    // even (b64 aligned), mirror 2-way conflict
static constexpr int OFF_A  = 0;                     // max(64*66, 32*104) = 4224
static constexpr int A_FL   = 64 * V_S;
static constexpr int OFF_W  = OFF_A  + A_FL;         // 64x96  W = V F
static constexpr int OFF_QX = OFF_W  + 64 * 96;      // 32x64  saved Qux
static constexpr int OFF_q  = OFF_QX + 32 * 64;      // 64  (qx only)
static constexpr int OFF_v  = OFF_q  + 64;           // 64
static constexpr int OFF_kv = OFF_v  + 64;           // 32
static constexpr int OFF_di = OFF_kv + 32;           // 32
static constexpr int OFF_FC = OFF_di + 32;           // 2 x (8x96) double-buffered F chunks
static constexpr int BK_FLOATS = OFF_FC + 2 * 8 * 96;  // 14144
static constexpr int BK_SMEM = BK_FLOATS * 4;        // 56576 B -> 4 CTAs/SM

__global__ void __launch_bounds__(256, 4)
backward_kernel(const float* __restrict__ C, const float* __restrict__ F) {
    extern __shared__ float sm[];
    float* sV   = sm + OFF_A;    // stride V_S
    float* sAug = sm + OFF_A;    // stride 104 (overlays V)
    float* sW   = sm + OFF_W;    // stride 96
    float* sQxS = sm + OFF_QX;   // stride 64
    float* sq   = sm + OFF_q;    // qx
    float* sv   = sm + OFF_v;
    float* skv  = sm + OFF_kv;
    float* sdin = sm + OFF_di;
    float* sFc  = sm + OFF_FC;   // 2 x 768 floats

    int b = blockIdx.x;
    int tid = threadIdx.x, lane = tid & 31, w = tid >> 5;
    unsigned fcbase = (unsigned)__cvta_generic_to_shared(sFc);

    // init V = 0, v = 0
    for (int i = tid; i < A_FL; i += 256) sV[i] = 0.f;
    if (tid < NS_) sv[tid] = 0.f;
    __syncthreads();

    for (int t = T_ - 1; t >= 0; t--) {
        size_t tb = (size_t)t * B_ + b;
        const float* Cb = C + tb * SZ_ * SZ_;
        const float* Fb = F + tb * NS_ * SZ_;
        const bool haveV = (t != T_ - 1);   // V==0 on the first backward step

        // ---- Phase A: W = V F (async-pipelined F) + q accumulation
        float qacc = 0.f;
        if (haveV) {
            int m0 = w * 8;
            ull acc[4][3];
#pragma unroll
            for (int p = 0; p < 4; p++) { acc[p][0] = 0; acc[p][1] = 0; acc[p][2] = 0; }
            // prefetch chunk 0 -> buf 0
            if (tid < 192) cp_async16(fcbase + tid * 16, Fb + tid * 4);
            cp_commit();
            for (int ch = 0; ch < 8; ch++) {
                cp_wait0();
                __syncthreads();
                if (ch < 7) {
                    if (tid < 192)
                        cp_async16(fcbase + ((ch + 1) & 1) * 3072 + tid * 16,
                                   Fb + (ch + 1) * 768 + tid * 4);
                    cp_commit();
                }
                const float* fc = sFc + (ch & 1) * 768;
#pragma unroll
                for (int nn = 0; nn < 8; nn++) {
                    int n = ch * 8 + nn;
                    const float* fr = fc + nn * 96;
                    float b0 = fr[lane];
                    float b1 = fr[lane + 32];
                    float b2 = fr[lane + 64];
                    ull bb0 = pack2(b0, b0), bb1 = pack2(b1, b1), bb2 = pack2(b2, b2);
                    const ull* xv = (const ull*)&sV[n * V_S + m0];
#pragma unroll
                    for (int p = 0; p < 4; p++) {
                        ull xx = xv[p];
                        fma2(acc[p][0], xx, bb0);
                        fma2(acc[p][1], xx, bb1);
                        fma2(acc[p][2], xx, bb2);
                    }
                    if (tid < SZ_) qacc += fr[tid] * sv[n];
                }
            }
            // write W
#pragma unroll
            for (int p = 0; p < 4; p++) {
                int m = m0 + 2 * p;
                float2 c0 = unpack2(acc[p][0]);
                float2 c1 = unpack2(acc[p][1]);
                float2 c2 = unpack2(acc[p][2]);
                sW[m * 96 + lane]            = c0.x;
                sW[(m + 1) * 96 + lane]      = c0.y;
                sW[m * 96 + lane + 32]       = c1.x;
                sW[(m + 1) * 96 + lane + 32] = c1.y;
                sW[m * 96 + lane + 64]       = c2.x;
                sW[(m + 1) * 96 + lane + 64] = c2.y;
            }
        }
        float rq = 0.f;
        if (tid < SZ_) {
            rq = qacc + g_cback[tb * SZ_ + tid];
            if (tid < NS_) sq[tid] = rq;
        }
        __syncthreads();   // V dead; W visible; region A becomes Aug
        if (tid >= NS_ && tid < SZ_) sAug[(tid - NS_) * AUG_S + 96] = rq;   // qu

        // ---- Phase B (fused): Q = C + F^T W for ALL 96 rows in one async F pass.
        // Rows 64..95 -> Aug/QxS now; rows 0..63 triangle -> registers (accx) across GJ.
        int i0 = w * 4;
        ull accx[4][2];
#pragma unroll
        for (int p = 0; p < 4; p++) { accx[p][0] = 0; accx[p][1] = 0; }
        {
            ull acc2[2][3];
#pragma unroll
            for (int p = 0; p < 2; p++) { acc2[p][0] = 0; acc2[p][1] = 0; acc2[p][2] = 0; }
            if (haveV) {
                if (tid < 192) cp_async16(fcbase + tid * 16, Fb + tid * 4);
                cp_commit();
                for (int ch = 0; ch < 8; ch++) {
                    cp_wait0();
                    __syncthreads();
                    if (ch < 7) {
                        if (tid < 192)
                            cp_async16(fcbase + ((ch + 1) & 1) * 3072 + tid * 16,
                                       Fb + (ch + 1) * 768 + tid * 4);
                        cp_commit();
                    }
                    const float* fc0 = sFc + (ch & 1) * 768;
#pragma unroll
                    for (int nn = 0; nn < 8; nn++) {
                        int n = ch * 8 + nn;
                        const float* wr = sW + n * 96;
                        float b0 = wr[lane];
                        float b1 = wr[lane + 32];
                        float b2 = wr[lane + 64];
                        ull bb0 = pack2(b0, b0), bb1 = pack2(b1, b1), bb2 = pack2(b2, b2);
                        const float* fc = fc0 + nn * 96;
                        ull xa0 = *(const ull*)(fc + 64 + i0);
                        ull xa1 = *(const ull*)(fc + 64 + i0 + 2);
                        fma2(acc2[0][0], xa0, bb0); fma2(acc2[0][1], xa0, bb1); fma2(acc2[0][2], xa0, bb2);
                        fma2(acc2[1][0], xa1, bb0); fma2(acc2[1][1], xa1, bb1); fma2(acc2[1][2], xa1, bb2);
#pragma unroll
                        for (int pp = 0; pp < 4; pp++) {
                            ull xx = *(const ull*)(fc + 2 * (w + 8 * pp));
                            fma2(accx[pp][0], xx, bb0);
                            if (pp >= 2) fma2(accx[pp][1], xx, bb1);
                        }
                    }
                }
            }
            // GEMM2 epilogue -> Aug / QxS (+ C rows 64..95)
#pragma unroll
            for (int p = 0; p < 2; p++) {
                int i = i0 + 2 * p;
                float2 c0 = unpack2(acc2[p][0]);   // s = lane       (Qux)
                float2 c1 = unpack2(acc2[p][1]);   // s = lane + 32  (Qux)
                float2 c2 = unpack2(acc2[p][2]);   // s = lane + 64  (Quu)
                float v00 = c0.x + Cb[(64 + i) * 96 + lane];
                float v10 = c0.y + Cb[(64 + i + 1) * 96 + lane];
                float v01 = c1.x + Cb[(64 + i) * 96 + lane + 32];
                float v11 = c1.y + Cb[(64 + i + 1) * 96 + lane + 32];
                float v02 = c2.x + Cb[(64 + i) * 96 + lane + 64];
                float v12 = c2.y + Cb[(64 + i + 1) * 96 + lane + 64];
                sQxS[i * 64 + lane] = v00;            sAug[i * AUG_S + 32 + lane] = v00;
                sQxS[(i + 1) * 64 + lane] = v10;      sAug[(i + 1) * AUG_S + 32 + lane] = v10;
                sQxS[i * 64 + lane + 32] = v01;       sAug[i * AUG_S + 64 + lane] = v01;
                sQxS[(i + 1) * 64 + lane + 32] = v11; sAug[(i + 1) * AUG_S + 64 + lane] = v11;
                sAug[i * AUG_S + lane] = v02;
                sAug[(i + 1) * AUG_S + lane] = v12;
            }
        }
        __syncthreads();

        // ---- Gauss-Jordan (unnormalized; SPD, no pivoting; 1 barrier/pivot)
        {
            int r = tid >> 3, sub = tid & 7;
            for (int kp = 0; kp < 32; kp++) {
                if (r != kp) {
                    float f = __fdividef(sAug[r * AUG_S + kp], sAug[kp * AUG_S + kp]);
                    for (int j = kp + 1 + sub; j <= 96; j += 8)
                        sAug[r * AUG_S + j] -= f * sAug[kp * AUG_S + j];
                }
                __syncthreads();
            }
        }

        // diag inverses, k
        if (tid < 32) {
            float di = 1.0f / sAug[tid * AUG_S + tid];
            sdin[tid] = di;
            float kv = -sAug[tid * AUG_S + 96] * di;
            skv[tid] = kv;
            g_kv[tb * NC_ + tid] = kv;
        }
        __syncthreads();

        // K -> global only (smem K folded into V_new reads of Aug)
        {
            float* Kg = g_K + tb * NC_ * NS_;
            for (int i = tid; i < NC_ * NS_; i += 256) {
                int m = i >> 6, j = i & 63;
                Kg[i] = -sAug[m * AUG_S + 32 + j] * sdin[m];
            }
        }

        // ---- V_new finalize: accx += Qux^T K; add C; mirror-store lower triangle.
        {
#pragma unroll 4
            for (int m = 0; m < 32; m++) {
                float nd = -sdin[m];
                float b0 = nd * sAug[m * AUG_S + 32 + lane];        // K[m][lane]
                float b1 = nd * sAug[m * AUG_S + 64 + lane];        // K[m][lane+32]
                ull bb0 = pack2(b0, b0), bb1 = pack2(b1, b1);
#pragma unroll
                for (int pp = 0; pp < 4; pp++) {
                    ull xx = *(const ull*)&sQxS[m * 64 + 2 * (w + 8 * pp)];
                    fma2(accx[pp][0], xx, bb0);
                    if (pp >= 2) fma2(accx[pp][1], xx, bb1);
                }
            }
            // v_new partial (reads sq/sQxS/skv — outside region A)
            float vnew = 0.f;
            if (tid < NS_) {
                float a = sq[tid];
#pragma unroll 4
                for (int m = 0; m < 32; m++) a += sQxS[m * 64 + tid] * skv[m];
                vnew = a;
            }
            // add C (LDGs issued before the barrier so latency overlaps the wait)
            float sv0[4], sv1[4], sw0v[2], sw1v[2];
#pragma unroll
            for (int pp = 0; pp < 4; pp++) {
                int i = 2 * (w + 8 * pp);
                float2 c0 = unpack2(accx[pp][0]);
                sv0[pp] = c0.x + Cb[i * 96 + lane];
                sv1[pp] = c0.y + Cb[(i + 1) * 96 + lane];
                if (pp >= 2) {
                    float2 c1 = unpack2(accx[pp][1]);
                    sw0v[pp - 2] = c1.x + Cb[i * 96 + lane + 32];
                    sw1v[pp - 2] = c1.y + Cb[(i + 1) * 96 + lane + 32];
                }
            }
            __syncthreads();   // ALL Aug reads complete before region A is overwritten

#pragma unroll
            for (int pp = 0; pp < 4; pp++) {
                int i = 2 * (w + 8 * pp);
                int j = lane;
                if (j <= i)     sV[i * V_S + j]       = sv0[pp];
                if (j <  i)     sV[j * V_S + i]       = sv0[pp];
                if (j <= i + 1) sV[(i + 1) * V_S + j] = sv1[pp];
                if (j <  i + 1) sV[j * V_S + i + 1]   = sv1[pp];
                if (pp >= 2) {
                    int j2 = lane + 32;
                    if (j2 <= i)     sV[i * V_S + j2]       = sw0v[pp - 2];
                    if (j2 <  i)     sV[j2 * V_S + i]       = sw0v[pp - 2];
                    if (j2 <= i + 1) sV[(i + 1) * V_S + j2] = sw1v[pp - 2];
                    if (j2 <  i + 1) sV[j2 * V_S + i + 1]   = sw1v[pp - 2];
                }
            }
            if (tid < NS_) sv[tid] = vnew;
        }
        __syncthreads();
    }
}

// ---------------- rollout: base (alpha=0) and direction trajectories ----------------
__global__ void rollout_kernel(const float* __restrict__ x, const float* __restrict__ u,
                               const float* __restrict__ x_init, const float* __restrict__ F) {
    int b = blockIdx.x;
    int tid = threadIdx.x;   // 128
    __shared__ float sF[64 * 97];
    __shared__ float sK[32 * 65];
    __shared__ float sk[32], su[32], sxn[64];
    __shared__ float nx0[64], dx0[64], dnx[64];
    __shared__ float sz0[96], szd[96];
    __shared__ float nxn[64], dnxn[64];

    if (tid < 64) { nx0[tid] = x_init[b * 64 + tid]; dx0[tid] = 0.f; dnx[tid] = 0.f; }
    __syncthreads();

    for (int t = 0; t < T_; t++) {
        size_t tb = (size_t)t * B_ + b;
        const float* Fb = F + tb * NS_ * SZ_;
        const float4* F4 = (const float4*)Fb;
        for (int i4 = tid; i4 < NS_ * SZ_ / 4; i4 += 128) {
            float4 v = F4[i4];
            int e = i4 * 4; int r = e / 96; int cc = e % 96;
            float* dst = &sF[r * 97 + cc];
            dst[0] = v.x; dst[1] = v.y; dst[2] = v.z; dst[3] = v.w;
        }
        const float4* K4 = (const float4*)(g_K + tb * NC_ * NS_);
        for (int i4 = tid; i4 < NC_ * NS_ / 4; i4 += 128) {
            float4 v = K4[i4];
            int e = i4 * 4; int r = e >> 6; int cc = e & 63;
            float* dst = &sK[r * 65 + cc];
            dst[0] = v.x; dst[1] = v.y; dst[2] = v.z; dst[3] = v.w;
        }
        if (tid < NC_) { sk[tid] = g_kv[tb * NC_ + tid]; su[tid] = u[tb * NC_ + tid]; }
        int tn = (t < T_ - 1) ? t + 1 : T_ - 1;
        if (tid < NS_) sxn[tid] = x[((size_t)tn * B_ + b) * NS_ + tid];
        __syncthreads();

        // controls
        if (tid < NC_) {
            float a0 = su[tid], a1 = sk[tid];
#pragma unroll 8
            for (int n = 0; n < 64; n++) { float kk = sK[tid * 65 + n]; a0 += kk * dx0[n]; a1 += kk * dnx[n]; }
            sz0[64 + tid] = a0; szd[64 + tid] = a1;
        }
        if (tid < NS_) { sz0[tid] = nx0[tid]; szd[tid] = dnx[tid]; }
        __syncthreads();

        // record entry state+control
        if (tid < SZ_) { g_z0[tb * SZ_ + tid] = sz0[tid]; g_dz[tb * SZ_ + tid] = szd[tid]; }

        // next state
        if (tid < NS_) {
            float a0 = 0.f, a1 = 0.f;
            const float* fr = &sF[tid * 97];
#pragma unroll 8
            for (int s = 0; s < 96; s++) { float fv = fr[s]; a0 += fv * sz0[s]; a1 += fv * szd[s]; }
            nxn[tid] = a0; dnxn[tid] = a1;
        }
        __syncthreads();
        if (tid < NS_) { nx0[tid] = nxn[tid]; dx0[tid] = nxn[tid] - sxn[tid]; dnx[tid] = dnxn[tid]; }
        __syncthreads();
    }
}

// ---------------- cost quadratic coefficients: cost(a) = q0 + a q1 + a^2 q2 ----------------
__global__ void coef_kernel(const float* __restrict__ C, const float* __restrict__ c) {
    int tb = blockIdx.x;
    int tid = threadIdx.x;   // 96 threads, 3 warps
    __shared__ float sz[SZ_], sd[SZ_];
    __shared__ float sw0[3], sw1[3], sw2[3];

    sz[tid] = g_z0[(size_t)tb * SZ_ + tid];
    sd[tid] = g_dz[(size_t)tb * SZ_ + tid];
    __syncthreads();

    const float* col = C + (size_t)tb * SZ_ * SZ_ + tid;
    float y0 = 0.f, yd = 0.f;
#pragma unroll 8
    for (int j = 0; j < SZ_; j++) {
        float cij = col[j * SZ_];
        y0 += cij * sz[j];
        yd += cij * sd[j];
    }
    float cv = c[(size_t)tb * SZ_ + tid];
    float p0 = sz[tid] * (0.5f * y0 + cv);
    float p1 = sd[tid] * (y0 + cv);
    float p2 = 0.5f * sd[tid] * yd;

#pragma unroll
    for (int o = 16; o > 0; o >>= 1) {
        p0 += __shfl_down_sync(0xffffffffu, p0, o);
        p1 += __shfl_down_sync(0xffffffffu, p1, o);
        p2 += __shfl_down_sync(0xffffffffu, p2, o);
    }
    if ((tid & 31) == 0) { int w = tid >> 5; sw0[w] = p0; sw1[w] = p1; sw2[w] = p2; }
    __syncthreads();
    if (tid == 0) {
        g_q0[tb] = sw0[0] + sw0[1] + sw0[2];
        g_q1[tb] = sw1[0] + sw1[1] + sw1[2];
        g_q2[tb] = sw2[0] + sw2[1] + sw2[2];
    }
}

// ---------------- line search resolve + cost output ----------------
__global__ void ls_kernel(float* __restrict__ out_cost) {
    int b = threadIdx.x;  // 512
    float old = 0.f, A0 = 0.f, A1 = 0.f, A2 = 0.f;
    for (int t = 0; t < T_; t++) {
        int idx = t * B_ + b;
        old += g_costpart[idx];
        A0 += g_q0[idx]; A1 += g_q1[idx]; A2 += g_q2[idx];
    }
    float alpha = 1.f;
#pragma unroll
    for (int i = 0; i < 3; i++) {
        float cst = A0 + alpha * (A1 + alpha * A2);
        if (cst > old) alpha *= 0.5f;
    }
    float cur = A0 + alpha * (A1 + alpha * A2);
    g_alpha[b] = alpha;
    out_cost[b] = cur;
}

// ---------------- final outputs: new_x, new_u ----------------
__global__ void out_kernel(float* __restrict__ out) {
    size_t total = (size_t)T_ * B_ * SZ_;
    for (size_t idx = blockIdx.x * (size_t)blockDim.x + threadIdx.x; idx < total;
         idx += (size_t)gridDim.x * blockDim.x) {
        size_t tb = idx / SZ_;
        int s = (int)(idx % SZ_);
        int b = (int)(tb % B_);
        float val = g_z0[idx] + g_alpha[b] * g_dz[idx];
        if (s < NS_) out[tb * NS_ + s] = val;
        else         out[(size_t)T_ * B_ * NS_ + tb * NC_ + (s - NS_)] = val;
    }
}

// ---------------- launch ----------------
extern "C" void kernel_launch(void* const* d_in, const int* in_sizes, int n_in,
                              void* d_out, int out_size) {
    const float *x = nullptr, *u = nullptr, *xi = nullptr, *C = nullptr, *c = nullptr, *F = nullptr;
    for (int i = 0; i < n_in; i++) {
        long long s = in_sizes[i];
        const float* p = (const float*)d_in[i];
        if      (s == (long long)T_ * B_ * SZ_ * SZ_) C = p;
        else if (s == (long long)T_ * B_ * NS_ * SZ_) F = p;
        else if (s == (long long)T_ * B_ * SZ_)       c = p;
        else if (s == (long long)T_ * B_ * NS_)       x = p;
        else if (s == (long long)T_ * B_ * NC_)       u = p;
        else if (s == (long long)B_ * NS_)            xi = p;
    }
    float* out = (float*)d_out;

    cudaFuncSetAttribute(backward_kernel, cudaFuncAttributeMaxDynamicSharedMemorySize, BK_SMEM);

    prep_kernel<<<T_ * B_, 96>>>(x, u, C, c);
    backward_kernel<<<B_, 256, BK_SMEM>>>(C, F);
    rollout_kernel<<<B_, 128>>>(x, u, xi, F);
    coef_kernel<<<T_ * B_, 96>>>(C, c);
    ls_kernel<<<1, B_>>>(out + (size_t)T_ * B_ * (NS_ + NC_));
    out_kernel<<<4096, 256>>>(out);
}